// round 5
// baseline (speedup 1.0000x reference)
#include <cuda_runtime.h>
#include <cooperative_groups.h>
#include <math.h>
#include <stdint.h>

namespace cg = cooperative_groups;

#define N_NODES 384
#define H 256
#define Z 128
#define ED 128
#define AH 64
#define H4 1024
#define NE (N_NODES * N_NODES)

// ------------------------- scratch (device globals) -------------------------
__device__ float g_nodes[N_NODES * H];     // [384,256]
__device__ float g_Amat[N_NODES * H4];     // nodes@W1a + eg_b1   [384,1024]
__device__ float g_Bmat[N_NODES * H4];     // nodes@W1b           [384,1024]
__device__ float g_M[H4 * ED];             // eg_W2 @ [a0W1e | a1W1e] [1024,128]
__device__ float g_cbias[ED];              // eg_b2@[a0W1e|a1W1e] + [a0b1|a1b1]
__device__ float g_Xc0[N_NODES * AH];      // nodes @ a0W1x  [384,64]
__device__ float g_hid[(size_t)NE * ED];   // per-pair hidden, [s][d][128]
__device__ float g_Att0T[NE];              // attention matrix layer0, [d][s]
__device__ float g_agg0[N_NODES * H];
__device__ float g_x1[N_NODES * H];
__device__ float g_Xc1[N_NODES * AH];      // x1 @ a1W1x
__device__ float g_w[N_NODES];             // row sums of Att1

// ------------------------------- GRU kernel ---------------------------------
// 8-CTA cluster; CTA c owns h-indices [32c,32c+32). 256 threads: each of the
// 96 Whh rows is split across 2 threads (K halves) -> matvec LDS time halved.
#define GRU_CTAS 8
#define GRU_HPC (H / GRU_CTAS)     // 32
#define GRU_ROWS (3 * GRU_HPC)     // 96
#define WS_LD 260
#define GRU_SMEM ((GRU_ROWS * WS_LD + 2 * H + 2 * GRU_ROWS + 2 * GRU_ROWS) * 4)

__global__ void __cluster_dims__(GRU_CTAS, 1, 1)
gru_kernel(const float* __restrict__ z, const float* __restrict__ Wih,
           const float* __restrict__ Whh, const float* __restrict__ bih,
           const float* __restrict__ bhh) {
  extern __shared__ float smem[];
  cg::cluster_group cluster = cg::this_cluster();
  const int c = cluster.block_rank();
  const int tid = threadIdx.x;

  float* ws = smem;                        // [96][WS_LD]
  float* hbuf = ws + GRU_ROWS * WS_LD;     // [2][256]
  float* partial2 = hbuf + 2 * H;          // [192]
  float* gi = partial2 + 2 * GRU_ROWS;     // [96]
  float* bh = gi + GRU_ROWS;               // [96]

  for (int idx = tid; idx < GRU_ROWS * H; idx += blockDim.x) {
    int r = idx / H, k = idx % H;
    int g = r / GRU_HPC, i = r % GRU_HPC;
    int grow = g * H + c * GRU_HPC + i;
    ws[r * WS_LD + k] = Whh[grow * H + k];
  }
  for (int r = tid; r < GRU_ROWS; r += blockDim.x) {
    int g = r / GRU_HPC, i = r % GRU_HPC;
    int grow = g * H + c * GRU_HPC + i;
    float s = bih[grow];
    for (int k = 0; k < Z; k++) s += Wih[grow * Z + k] * z[k];
    gi[r] = s;
    bh[r] = bhh[grow];
  }
  for (int k = tid; k < H; k += blockDim.x) hbuf[k] = 0.f;
  __syncthreads();
  cluster.sync();

  const int row = tid >> 1, half = tid & 1;
  for (int step = 0; step < N_NODES; step++) {
    const int cur = step & 1, nxt = cur ^ 1;
    const float* h = hbuf + cur * H;
    if (tid < 2 * GRU_ROWS) {
      const float4* wrow = (const float4*)(ws + row * WS_LD + half * 128);
      const float4* hv = (const float4*)(h + half * 128);
      float a0 = 0.f, a1 = 0.f, a2 = 0.f, a3 = 0.f;
#pragma unroll
      for (int k4 = 0; k4 < 32; k4++) {
        float4 wv = wrow[k4];
        float4 hh = hv[k4];
        a0 += wv.x * hh.x;
        a1 += wv.y * hh.y;
        a2 += wv.z * hh.z;
        a3 += wv.w * hh.w;
      }
      partial2[tid] = (a0 + a1) + (a2 + a3);
    }
    __syncthreads();
    if (tid < GRU_HPC) {
      const int i = tid;
      float ghr = partial2[2 * i] + partial2[2 * i + 1] + bh[i];
      float ghz = partial2[2 * (GRU_HPC + i)] + partial2[2 * (GRU_HPC + i) + 1] +
                  bh[GRU_HPC + i];
      float ghn = partial2[2 * (2 * GRU_HPC + i)] +
                  partial2[2 * (2 * GRU_HPC + i) + 1] + bh[2 * GRU_HPC + i];
      float r = 1.f / (1.f + expf(-(gi[i] + ghr)));
      float u = 1.f / (1.f + expf(-(gi[GRU_HPC + i] + ghz)));
      float n = tanhf(gi[2 * GRU_HPC + i] + r * ghn);
      float h2 = (1.f - u) * n + u * h[c * GRU_HPC + i];
      g_nodes[step * H + c * GRU_HPC + i] = h2;
      for (int rk = 0; rk < GRU_CTAS; rk++) {
        float* remote = cluster.map_shared_rank(hbuf, rk);
        remote[nxt * H + c * GRU_HPC + i] = h2;
      }
    }
    cluster.sync();
  }
}

// --------------------------- generic fp32 GEMM ------------------------------
template <bool RELU>
__global__ void gemm_kernel(int M, int N, int K, const float* __restrict__ A,
                            int lda, const float* __restrict__ B, int ldb,
                            const float* __restrict__ bias,
                            float* __restrict__ C, int ldc) {
  __shared__ float As[16][68];
  __shared__ float Bs[16][68];
  const int tx = threadIdx.x % 16, ty = threadIdx.x / 16;
  const int m0 = blockIdx.y * 64, n0 = blockIdx.x * 64;
  float acc[4][4] = {};
  for (int k0 = 0; k0 < K; k0 += 16) {
    for (int idx = threadIdx.x; idx < 64 * 16; idx += 256) {
      int m = idx / 16, k = idx % 16;
      As[k][m] = A[(size_t)(m0 + m) * lda + k0 + k];
    }
    for (int idx = threadIdx.x; idx < 16 * 64; idx += 256) {
      int k = idx / 64, n = idx % 64;
      Bs[k][n] = B[(size_t)(k0 + k) * ldb + n0 + n];
    }
    __syncthreads();
#pragma unroll
    for (int k = 0; k < 16; k++) {
      float a[4], b[4];
#pragma unroll
      for (int i = 0; i < 4; i++) a[i] = As[k][ty * 4 + i];
#pragma unroll
      for (int j = 0; j < 4; j++) b[j] = Bs[k][tx * 4 + j];
#pragma unroll
      for (int i = 0; i < 4; i++)
#pragma unroll
        for (int j = 0; j < 4; j++) acc[i][j] += a[i] * b[j];
    }
    __syncthreads();
  }
#pragma unroll
  for (int i = 0; i < 4; i++) {
#pragma unroll
    for (int j = 0; j < 4; j++) {
      float v = acc[i][j] + (bias ? bias[n0 + tx * 4 + j] : 0.f);
      if (RELU) v = fmaxf(v, 0.f);
      C[(size_t)(m0 + ty * 4 + i) * ldc + n0 + tx * 4 + j] = v;
    }
  }
}

// ---------------- dual GEMM: blockIdx.z selects (B, C, bias) ----------------
__global__ void gemm_dual_kernel(int M, int N, int K, const float* __restrict__ A,
                                 int lda, const float* __restrict__ B0,
                                 const float* __restrict__ B1, int ldb,
                                 const float* __restrict__ bias0,
                                 float* __restrict__ C0, float* __restrict__ C1,
                                 int ldc) {
  const float* B = blockIdx.z ? B1 : B0;
  float* C = blockIdx.z ? C1 : C0;
  const float* bias = blockIdx.z ? nullptr : bias0;
  __shared__ float As[16][68];
  __shared__ float Bs[16][68];
  const int tx = threadIdx.x % 16, ty = threadIdx.x / 16;
  const int m0 = blockIdx.y * 64, n0 = blockIdx.x * 64;
  float acc[4][4] = {};
  for (int k0 = 0; k0 < K; k0 += 16) {
    for (int idx = threadIdx.x; idx < 64 * 16; idx += 256) {
      int m = idx / 16, k = idx % 16;
      As[k][m] = A[(size_t)(m0 + m) * lda + k0 + k];
    }
    for (int idx = threadIdx.x; idx < 16 * 64; idx += 256) {
      int k = idx / 64, n = idx % 64;
      Bs[k][n] = B[(size_t)(k0 + k) * ldb + n0 + n];
    }
    __syncthreads();
#pragma unroll
    for (int k = 0; k < 16; k++) {
      float a[4], b[4];
#pragma unroll
      for (int i = 0; i < 4; i++) a[i] = As[k][ty * 4 + i];
#pragma unroll
      for (int j = 0; j < 4; j++) b[j] = Bs[k][tx * 4 + j];
#pragma unroll
      for (int i = 0; i < 4; i++)
#pragma unroll
        for (int j = 0; j < 4; j++) acc[i][j] += a[i] * b[j];
    }
    __syncthreads();
  }
#pragma unroll
  for (int i = 0; i < 4; i++) {
#pragma unroll
    for (int j = 0; j < 4; j++) {
      float v = acc[i][j] + (bias ? bias[n0 + tx * 4 + j] : 0.f);
      C[(size_t)(m0 + ty * 4 + i) * ldc + n0 + tx * 4 + j] = v;
    }
  }
}

// ------------------------------ cbias kernel --------------------------------
__global__ void cbias_kernel(const float* __restrict__ egb2,
                             const float* __restrict__ a0W1,
                             const float* __restrict__ a0b1,
                             const float* __restrict__ a1W1,
                             const float* __restrict__ a1b1) {
  int cidx = threadIdx.x;  // 128
  float s;
  if (cidx < AH) {
    s = a0b1[cidx];
    for (int k = 0; k < ED; k++) s += egb2[k] * a0W1[k * AH + cidx];
  } else {
    int cc = cidx - AH;
    s = a1b1[cc];
    for (int k = 0; k < ED; k++) s += egb2[k] * a1W1[k * AH + cc];
  }
  g_cbias[cidx] = s;
}

// ----------------- fused edge-hidden GEMM via tf32 mma.sync -----------------
// hid[s][d][c] = relu(A[s]+B[d]) @ M[:,c] + cbias[c]
// Round-3 proven-correct fragment mapping + software-pipelined register
// prefetch: next chunk's LDGs are issued before the current chunk's MMA phase
// so L2 latency (~250cyc, all operands L2-resident) is hidden under MMAs.

__device__ __forceinline__ uint32_t f2tf(float x) {
  uint32_t r;
  asm("cvt.rna.tf32.f32 %0, %1;" : "=r"(r) : "f"(x));
  return r;
}

__device__ __forceinline__ void mma_tf32(float& d0, float& d1, float& d2,
                                         float& d3, uint32_t a0, uint32_t a1,
                                         uint32_t a2, uint32_t a3, uint32_t b0,
                                         uint32_t b1) {
  asm volatile(
      "mma.sync.aligned.m16n8k8.row.col.f32.tf32.tf32.f32 "
      "{%0,%1,%2,%3},{%4,%5,%6,%7},{%8,%9},{%0,%1,%2,%3};"
      : "+f"(d0), "+f"(d1), "+f"(d2), "+f"(d3)
      : "r"(a0), "r"(a1), "r"(a2), "r"(a3), "r"(b0), "r"(b1));
}

#define EKC 16
#define ENCHUNK (H4 / EKC)  // 64
#define TS_LD 20

__global__ void __launch_bounds__(256, 2) edge_mma_kernel() {
  __shared__ float asv[H4];
  __shared__ uint32_t Ts[128 * TS_LD];
  __shared__ uint32_t Ms[128 * TS_LD];
  const int s = blockIdx.y;
  const int d0 = blockIdx.x * 128;
  const int tid = threadIdx.x;
  const int warp = tid >> 5, lane = tid & 31;
  const int wm = warp & 1, wn = warp >> 1;  // 2 x 4 warp grid
  const int m0w = wm * 64, n0w = wn * 32;
  const int g4 = lane >> 2, t4 = lane & 3;

  for (int i = tid; i < H4; i += 256) asv[i] = g_Amat[(size_t)s * H4 + i];
  __syncthreads();

  // per-thread staging coordinates (fixed)
  const int kk4l = (tid & 3) * 4;          // T staging: k base in {0,4,8,12}
  const int th = (kk4l >> 2) & 1;          // perm offset
  const int tbase8 = (kk4l >> 3) * 8;
  const int tdd = tid >> 2;                // 0..63

  float4 pb[2];
  float pm[8];
  // prefetch chunk 0
#pragma unroll
  for (int it = 0; it < 2; it++)
    pb[it] = *(const float4*)&g_Bmat[(size_t)(d0 + it * 64 + tdd) * H4 + kk4l];
#pragma unroll
  for (int i = 0; i < 8; i++) {
    const int e = i * 256 + tid;
    pm[i] = g_M[(size_t)(e >> 7) * ED + (e & 127)];
  }

  float acc[4][4][4] = {};  // [mi][ni][frag]

  for (int chunk = 0; chunk < ENCHUNK; chunk++) {
    const int k0 = chunk * EKC;
    // stage current chunk from prefetch regs
    {
      const float* av = &asv[k0 + kk4l];
#pragma unroll
      for (int it = 0; it < 2; it++) {
        uint32_t* rowp = &Ts[(it * 64 + tdd) * TS_LD + tbase8 + th];
        rowp[0] = f2tf(fmaxf(av[0] + pb[it].x, 0.f));
        rowp[2] = f2tf(fmaxf(av[1] + pb[it].y, 0.f));
        rowp[4] = f2tf(fmaxf(av[2] + pb[it].z, 0.f));
        rowp[6] = f2tf(fmaxf(av[3] + pb[it].w, 0.f));
      }
#pragma unroll
      for (int i = 0; i < 8; i++) {
        const int e = i * 256 + tid;
        const int kk = e >> 7, c = e & 127;
        const int pos = (kk >> 3) * 8 + (kk & 3) * 2 + ((kk >> 2) & 1);
        Ms[c * TS_LD + pos] = f2tf(pm[i]);
      }
    }
    __syncthreads();
    // prefetch next chunk while MMAs run
    if (chunk + 1 < ENCHUNK) {
      const int kn = k0 + EKC;
#pragma unroll
      for (int it = 0; it < 2; it++)
        pb[it] = *(const float4*)&g_Bmat[(size_t)(d0 + it * 64 + tdd) * H4 +
                                         kn + kk4l];
#pragma unroll
      for (int i = 0; i < 8; i++) {
        const int e = i * 256 + tid;
        pm[i] = g_M[(size_t)(kn + (e >> 7)) * ED + (e & 127)];
      }
    }
#pragma unroll
    for (int k8 = 0; k8 < 2; k8++) {
      const int kb = k8 * 8 + t4 * 2;
      uint32_t af[4][4], bf[4][2];
#pragma unroll
      for (int mi = 0; mi < 4; mi++) {
        const int r = m0w + mi * 16 + g4;
        uint2 x = *(const uint2*)&Ts[r * TS_LD + kb];
        uint2 y = *(const uint2*)&Ts[(r + 8) * TS_LD + kb];
        af[mi][0] = x.x; af[mi][1] = y.x; af[mi][2] = x.y; af[mi][3] = y.y;
      }
#pragma unroll
      for (int ni = 0; ni < 4; ni++) {
        const int c = n0w + ni * 8 + g4;
        uint2 b = *(const uint2*)&Ms[c * TS_LD + kb];
        bf[ni][0] = b.x; bf[ni][1] = b.y;
      }
#pragma unroll
      for (int mi = 0; mi < 4; mi++)
#pragma unroll
        for (int ni = 0; ni < 4; ni++)
          mma_tf32(acc[mi][ni][0], acc[mi][ni][1], acc[mi][ni][2],
                   acc[mi][ni][3], af[mi][0], af[mi][1], af[mi][2], af[mi][3],
                   bf[ni][0], bf[ni][1]);
    }
    __syncthreads();
  }

  // epilogue: + cbias, store
#pragma unroll
  for (int ni = 0; ni < 4; ni++) {
    const int ch = n0w + ni * 8 + t4 * 2;
    float2 cb = *(const float2*)&g_cbias[ch];
#pragma unroll
    for (int mi = 0; mi < 4; mi++) {
      const int d = d0 + m0w + mi * 16 + g4;
      float2 o0, o1;
      o0.x = acc[mi][ni][0] + cb.x;
      o0.y = acc[mi][ni][1] + cb.y;
      o1.x = acc[mi][ni][2] + cb.x;
      o1.y = acc[mi][ni][3] + cb.y;
      *(float2*)&g_hid[(((size_t)s) * N_NODES + d) * ED + ch] = o0;
      *(float2*)&g_hid[(((size_t)s) * N_NODES + d + 8) * ED + ch] = o1;
    }
  }
}

// --------------------------- attention layer 0 ------------------------------
__global__ void att0_kernel(const float* __restrict__ a0W2,
                            const float* __restrict__ a0b2) {
  const int s = blockIdx.x;
  const int warp = threadIdx.x >> 5, lane = threadIdx.x & 31;
  __shared__ float xc[AH], w2[AH];
  if (threadIdx.x < AH) {
    xc[threadIdx.x] = g_Xc0[s * AH + threadIdx.x];
    w2[threadIdx.x] = a0W2[threadIdx.x];
  }
  __syncthreads();
  const float b2 = a0b2[0];
  for (int d = warp; d < N_NODES; d += 8) {
    float2 h2 = *(const float2*)&g_hid[(((size_t)s) * N_NODES + d) * ED + lane * 2];
    float v = fmaxf(h2.x + xc[lane * 2], 0.f) * w2[lane * 2] +
              fmaxf(h2.y + xc[lane * 2 + 1], 0.f) * w2[lane * 2 + 1];
    for (int o = 16; o > 0; o >>= 1) v += __shfl_down_sync(0xffffffffu, v, o);
    if (lane == 0) {
      float att = (d == s) ? 0.f : 1.f / (1.f + expf(-(v + b2)));
      g_Att0T[(size_t)d * N_NODES + s] = att;
    }
  }
}

// ------------------ attention layer 1 row-sums w[s] -------------------------
__global__ void att1w_kernel(const float* __restrict__ a1W2,
                             const float* __restrict__ a1b2) {
  const int s = blockIdx.x;
  const int warp = threadIdx.x >> 5, lane = threadIdx.x & 31;
  __shared__ float xc[AH], w2[AH];
  __shared__ float wsum[8];
  if (threadIdx.x < AH) {
    xc[threadIdx.x] = g_Xc1[s * AH + threadIdx.x];
    w2[threadIdx.x] = a1W2[threadIdx.x];
  }
  __syncthreads();
  const float b2 = a1b2[0];
  float accv = 0.f;
  for (int d = warp; d < N_NODES; d += 8) {
    float2 h2 =
        *(const float2*)&g_hid[(((size_t)s) * N_NODES + d) * ED + AH + lane * 2];
    float v = fmaxf(h2.x + xc[lane * 2], 0.f) * w2[lane * 2] +
              fmaxf(h2.y + xc[lane * 2 + 1], 0.f) * w2[lane * 2 + 1];
    for (int o = 16; o > 0; o >>= 1) v += __shfl_down_sync(0xffffffffu, v, o);
    if (lane == 0 && d != s) accv += 1.f / (1.f + expf(-(v + b2)));
  }
  if (lane == 0) wsum[warp] = accv;
  __syncthreads();
  if (threadIdx.x == 0) {
    float t = 0.f;
    for (int i = 0; i < 8; i++) t += wsum[i];
    g_w[s] = t;
  }
}

// --------------------------- final reduction --------------------------------
__global__ void final_kernel(const float* __restrict__ c1W,
                             const float* __restrict__ c1b,
                             float* __restrict__ out) {
  __shared__ float v[H];
  __shared__ float wsh[N_NODES];
  const int tid = threadIdx.x;  // 256
  for (int i = tid; i < N_NODES; i += blockDim.x) wsh[i] = g_w[i];
  __syncthreads();
  float s = 0.f;
  for (int n = 0; n < N_NODES; n++) s += wsh[n] * g_x1[n * H + tid];
  v[tid] = s;
  __syncthreads();
  float o = (float)N_NODES * c1b[tid];
  for (int h = 0; h < H; h++) o += v[h] * c1W[h * H + tid];
  out[tid] = o;
}

// ------------------------------- launcher -----------------------------------
static float* sym_addr(const void* symbol) {
  void* p = nullptr;
  cudaGetSymbolAddress(&p, symbol);
  return (float*)p;
}

extern "C" void kernel_launch(void* const* d_in, const int* in_sizes, int n_in,
                              void* d_out, int out_size) {
  const float* z = (const float*)d_in[0];
  const float* Wih = (const float*)d_in[1];
  const float* Whh = (const float*)d_in[2];
  const float* bih = (const float*)d_in[3];
  const float* bhh = (const float*)d_in[4];
  const float* egW1 = (const float*)d_in[5];
  const float* egb1 = (const float*)d_in[6];
  const float* egW2 = (const float*)d_in[7];
  const float* egb2 = (const float*)d_in[8];
  const float* a0W1 = (const float*)d_in[9];
  const float* a0b1 = (const float*)d_in[10];
  const float* a0W2 = (const float*)d_in[11];
  const float* a0b2 = (const float*)d_in[12];
  const float* a1W1 = (const float*)d_in[13];
  const float* a1b1 = (const float*)d_in[14];
  const float* a1W2 = (const float*)d_in[15];
  const float* a1b2 = (const float*)d_in[16];
  const float* c0W = (const float*)d_in[17];
  const float* c0b = (const float*)d_in[18];
  const float* c1W = (const float*)d_in[19];
  const float* c1b = (const float*)d_in[20];
  float* out = (float*)d_out;

  cudaFuncSetAttribute(gru_kernel, cudaFuncAttributeMaxDynamicSharedMemorySize,
                       GRU_SMEM);

  float* nodes = sym_addr(g_nodes);
  float* Amat = sym_addr(g_Amat);
  float* Bmat = sym_addr(g_Bmat);
  float* Mmat = sym_addr(g_M);
  float* Xc0 = sym_addr(g_Xc0);
  float* Att0T = sym_addr(g_Att0T);
  float* agg0 = sym_addr(g_agg0);
  float* x1 = sym_addr(g_x1);
  float* Xc1 = sym_addr(g_Xc1);

  // launch 0: GRU -> nodes
  gru_kernel<<<GRU_CTAS, 256, GRU_SMEM>>>(z, Wih, Whh, bih, bhh);

  // launch 1: A = nodes@W1a + eg_b1 ; B = nodes@W1b (z selects half)
  gemm_dual_kernel<<<dim3(H4 / 64, N_NODES / 64, 2), 256>>>(
      N_NODES, H4, H, nodes, H, egW1, egW1 + (size_t)H * H4, H4, egb1, Amat,
      Bmat, H4);

  // launch 2: M = eg_W2 @ [a0W1e | a1W1e] (z selects column half)
  gemm_dual_kernel<<<dim3(1, H4 / 64, 2), 256>>>(
      H4, AH, ED, egW2, ED, a0W1, a1W1, AH, nullptr, Mmat, Mmat + AH, ED);

  // launch 3: cbias
  cbias_kernel<<<1, ED>>>(egb2, a0W1, a0b1, a1W1, a1b1);

  // launch 4: Xc0 = nodes @ a0W1x
  gemm_kernel<false><<<dim3(1, N_NODES / 64), 256>>>(
      N_NODES, AH, H, nodes, H, a0W1 + (size_t)ED * AH, AH, nullptr, Xc0, AH);

  // launch 5 (PROFILED by ncu -s 5 -c 1): pairwise edge-hidden GEMM
  edge_mma_kernel<<<dim3(N_NODES / 128, N_NODES), 256>>>();

  // launch 6: attention layer 0 -> Att0T [d][s]
  att0_kernel<<<N_NODES, 256>>>(a0W2, a0b2);

  // launch 7-8: agg0 = Att0T @ nodes ; x1 = relu(agg0 @ c0W + c0b)
  gemm_kernel<false><<<dim3(H / 64, N_NODES / 64), 256>>>(
      N_NODES, H, N_NODES, Att0T, N_NODES, nodes, H, nullptr, agg0, H);
  gemm_kernel<true><<<dim3(H / 64, N_NODES / 64), 256>>>(
      N_NODES, H, H, agg0, H, c0W, H, c0b, x1, H);

  // launch 9: Xc1 = x1 @ a1W1x
  gemm_kernel<false><<<dim3(1, N_NODES / 64), 256>>>(
      N_NODES, AH, H, x1, H, a1W1 + (size_t)ED * AH, AH, nullptr, Xc1, AH);

  // launch 10: w[s] = sum_d att1(s,d)
  att1w_kernel<<<N_NODES, 256>>>(a1W2, a1b2);

  // launch 11: out = (sum_s w[s] x1[s]) @ c1W + 384*c1b
  final_kernel<<<1, H>>>(c1W, c1b, out);
}

// round 8
// speedup vs baseline: 1.4590x; 1.4590x over previous
#include <cuda_runtime.h>
#include <cooperative_groups.h>
#include <math.h>
#include <stdint.h>

namespace cg = cooperative_groups;

#define N_NODES 384
#define H 256
#define Z 128
#define ED 128
#define AH 64
#define H4 1024
#define NE (N_NODES * N_NODES)

// ------------------------- scratch (device globals) -------------------------
__device__ float g_nodes[N_NODES * H];       // [384,256]
__device__ float g_Amat[N_NODES * H4];       // nodes@W1a + eg_b1
__device__ float g_Bmat[N_NODES * H4];       // nodes@W1b
__device__ float g_Mdup[H4 * 2 * ED];        // M = egW2@[a0W1e|a1W1e], each ch duplicated
__device__ float g_hid1[(size_t)NE * AH];    // att1 half of hidden (raw), [s][d][64]
__device__ float g_Att0T[NE];                // att0 matrix, [d][s]
__device__ float g_agg0[N_NODES * H];
__device__ float g_x1[N_NODES * H];
__device__ float g_w[N_NODES];

// --------------------------- packed f32x2 helpers ---------------------------
__device__ __forceinline__ void ffma2(unsigned long long& acc,
                                      unsigned long long a,
                                      unsigned long long b) {
  asm("fma.rn.f32x2 %0, %1, %2, %0;" : "+l"(acc) : "l"(a), "l"(b));
}
__device__ __forceinline__ float2 up2(unsigned long long v) {
  float2 r;
  r.x = __uint_as_float((unsigned)(v & 0xffffffffull));
  r.y = __uint_as_float((unsigned)(v >> 32));
  return r;
}

// ------------------------------- GRU kernel ---------------------------------
// 8-CTA cluster, 384 threads. Whh register-resident: warp w, lane l handles
// row r=(w%3)*32+l (gate g=w%3, idx l), k-quarter kq=w/3 (64 k, 32 packed regs).
// h read via broadcast LDS (all lanes same addr), h2 broadcast via DSMEM.
#define GRU_CTAS 8
#define GRU_HPC 32
#define GRU_ROWS 96

__global__ void __cluster_dims__(GRU_CTAS, 1, 1) __launch_bounds__(384)
gru_kernel(const float* __restrict__ z, const float* __restrict__ Wih,
           const float* __restrict__ Whh, const float* __restrict__ bih,
           const float* __restrict__ bhh) {
  __shared__ float hbuf[2][H];
  __shared__ float part[4 * GRU_ROWS];
  __shared__ float gi[GRU_ROWS];
  __shared__ float bh[GRU_ROWS];
  cg::cluster_group cluster = cg::this_cluster();
  const int c = cluster.block_rank();
  const int tid = threadIdx.x;
  const int w = tid >> 5, l = tid & 31;
  const int gate = w % 3, kq = w / 3;        // kq in 0..3
  const int r = gate * 32 + l;               // local row 0..95
  const int grow = gate * H + c * GRU_HPC + l;

  // weights for this thread: Whh[grow][kq*64 .. +64) as 32 packed f32x2
  unsigned long long wr[32];
  {
    const float* wsrc = &Whh[(size_t)grow * H + kq * 64];
#pragma unroll
    for (int j = 0; j < 16; j++) {
      ulonglong2 t = *(const ulonglong2*)&wsrc[j * 4];
      wr[2 * j] = t.x;
      wr[2 * j + 1] = t.y;
    }
  }
  // gi = Wih@z + bih, bh
  for (int rr = tid; rr < GRU_ROWS; rr += 384) {
    int g2 = rr >> 5, i2 = rr & 31;
    int gr = g2 * H + c * GRU_HPC + i2;
    float s = bih[gr];
    for (int k = 0; k < Z; k++) s += Wih[gr * Z + k] * z[k];
    gi[rr] = s;
    bh[rr] = bhh[gr];
  }
  for (int k = tid; k < 2 * H; k += 384) hbuf[0][k] = 0.f;
  __syncthreads();
  cluster.sync();

  for (int step = 0; step < N_NODES; step++) {
    const int cur = step & 1, nxt = cur ^ 1;
    {
      const float* hsrc = &hbuf[cur][kq * 64];
      unsigned long long a0 = 0, a1 = 0, a2 = 0, a3 = 0;
#pragma unroll
      for (int j = 0; j < 16; j += 2) {
        ulonglong2 hv0 = *(const ulonglong2*)&hsrc[j * 4];
        ulonglong2 hv1 = *(const ulonglong2*)&hsrc[j * 4 + 4];
        ffma2(a0, wr[2 * j], hv0.x);
        ffma2(a1, wr[2 * j + 1], hv0.y);
        ffma2(a2, wr[2 * j + 2], hv1.x);
        ffma2(a3, wr[2 * j + 3], hv1.y);
      }
      float2 s0 = up2(a0), s1 = up2(a1), s2 = up2(a2), s3 = up2(a3);
      part[kq * GRU_ROWS + r] =
          ((s0.x + s0.y) + (s1.x + s1.y)) + ((s2.x + s2.y) + (s3.x + s3.y));
    }
    __syncthreads();
    if (tid < GRU_HPC) {
      const int i = tid;
      float ghr = part[i] + part[96 + i] + part[192 + i] + part[288 + i] + bh[i];
      float ghz = part[32 + i] + part[96 + 32 + i] + part[192 + 32 + i] +
                  part[288 + 32 + i] + bh[32 + i];
      float ghn = part[64 + i] + part[96 + 64 + i] + part[192 + 64 + i] +
                  part[288 + 64 + i] + bh[64 + i];
      float rg = 1.f / (1.f + expf(-(gi[i] + ghr)));
      float ug = 1.f / (1.f + expf(-(gi[32 + i] + ghz)));
      float ng = tanhf(gi[64 + i] + rg * ghn);
      float h2 = (1.f - ug) * ng + ug * hbuf[cur][c * GRU_HPC + i];
      g_nodes[step * H + c * GRU_HPC + i] = h2;
#pragma unroll
      for (int rk = 0; rk < GRU_CTAS; rk++) {
        float* remote = (float*)cluster.map_shared_rank(hbuf, rk);
        remote[nxt * H + c * GRU_HPC + i] = h2;
      }
    }
    cluster.sync();
  }
}

// --------------------------- generic fp32 GEMM ------------------------------
template <bool RELU>
__global__ void gemm_kernel(int M, int N, int K, const float* __restrict__ A,
                            int lda, const float* __restrict__ B, int ldb,
                            const float* __restrict__ bias,
                            float* __restrict__ C, int ldc) {
  __shared__ float As[16][68];
  __shared__ float Bs[16][68];
  const int tx = threadIdx.x % 16, ty = threadIdx.x / 16;
  const int m0 = blockIdx.y * 64, n0 = blockIdx.x * 64;
  float acc[4][4] = {};
  for (int k0 = 0; k0 < K; k0 += 16) {
    for (int idx = threadIdx.x; idx < 64 * 16; idx += 256) {
      int m = idx / 16, k = idx % 16;
      As[k][m] = A[(size_t)(m0 + m) * lda + k0 + k];
    }
    for (int idx = threadIdx.x; idx < 16 * 64; idx += 256) {
      int k = idx / 64, n = idx % 64;
      Bs[k][n] = B[(size_t)(k0 + k) * ldb + n0 + n];
    }
    __syncthreads();
#pragma unroll
    for (int k = 0; k < 16; k++) {
      float a[4], b[4];
#pragma unroll
      for (int i = 0; i < 4; i++) a[i] = As[k][ty * 4 + i];
#pragma unroll
      for (int j = 0; j < 4; j++) b[j] = Bs[k][tx * 4 + j];
#pragma unroll
      for (int i = 0; i < 4; i++)
#pragma unroll
        for (int j = 0; j < 4; j++) acc[i][j] += a[i] * b[j];
    }
    __syncthreads();
  }
#pragma unroll
  for (int i = 0; i < 4; i++) {
#pragma unroll
    for (int j = 0; j < 4; j++) {
      float v = acc[i][j] + (bias ? bias[n0 + tx * 4 + j] : 0.f);
      if (RELU) v = fmaxf(v, 0.f);
      C[(size_t)(m0 + ty * 4 + i) * ldc + n0 + tx * 4 + j] = v;
    }
  }
}

// ---------------- dual GEMM: blockIdx.z selects (B, C, bias) ----------------
// DUP: write each output twice at consecutive columns (for g_Mdup).
template <bool DUP>
__global__ void gemm_dual_kernel(int M, int N, int K, const float* __restrict__ A,
                                 int lda, const float* __restrict__ B0,
                                 const float* __restrict__ B1, int ldb,
                                 const float* __restrict__ bias0,
                                 float* __restrict__ C0, float* __restrict__ C1,
                                 int ldc) {
  const float* B = blockIdx.z ? B1 : B0;
  float* C = blockIdx.z ? C1 : C0;
  const float* bias = blockIdx.z ? nullptr : bias0;
  __shared__ float As[16][68];
  __shared__ float Bs[16][68];
  const int tx = threadIdx.x % 16, ty = threadIdx.x / 16;
  const int m0 = blockIdx.y * 64, n0 = blockIdx.x * 64;
  float acc[4][4] = {};
  for (int k0 = 0; k0 < K; k0 += 16) {
    for (int idx = threadIdx.x; idx < 64 * 16; idx += 256) {
      int m = idx / 16, k = idx % 16;
      As[k][m] = A[(size_t)(m0 + m) * lda + k0 + k];
    }
    for (int idx = threadIdx.x; idx < 16 * 64; idx += 256) {
      int k = idx / 64, n = idx % 64;
      Bs[k][n] = B[(size_t)(k0 + k) * ldb + n0 + n];
    }
    __syncthreads();
#pragma unroll
    for (int k = 0; k < 16; k++) {
      float a[4], b[4];
#pragma unroll
      for (int i = 0; i < 4; i++) a[i] = As[k][ty * 4 + i];
#pragma unroll
      for (int j = 0; j < 4; j++) b[j] = Bs[k][tx * 4 + j];
#pragma unroll
      for (int i = 0; i < 4; i++)
#pragma unroll
        for (int j = 0; j < 4; j++) acc[i][j] += a[i] * b[j];
    }
    __syncthreads();
  }
#pragma unroll
  for (int i = 0; i < 4; i++) {
#pragma unroll
    for (int j = 0; j < 4; j++) {
      float v = acc[i][j] + (bias ? bias[n0 + tx * 4 + j] : 0.f);
      const int mm = m0 + ty * 4 + i, nn = n0 + tx * 4 + j;
      if (DUP) {
        C[(size_t)mm * ldc + 2 * nn] = v;
        C[(size_t)mm * ldc + 2 * nn + 1] = v;
      } else {
        C[(size_t)mm * ldc + nn] = v;
      }
    }
  }
}

// ------------------- f32x2 edge GEMM + fused attention-0 --------------------
// Per CTA: s = blockIdx.y, d-tile [d0,d0+128), all 128 ch.
// P[d][c] = relu(A[s]+B[d]) @ M[:,c]. Thread tile 16d x 4ch, packed over d.
// Epilogue: ch<64 -> att0 (smem reduce); ch>=64 -> store raw hid1.
#define ETS_LD 160

__global__ void __launch_bounds__(256, 2) edge_kernel(
    const float* __restrict__ a0W1, const float* __restrict__ a0b1,
    const float* __restrict__ a0W2, const float* __restrict__ a0b2,
    const float* __restrict__ egb2) {
  __shared__ float asv[H4];
  __shared__ float Ts[16][ETS_LD];       // T tile, skewed: col(d)=d+((d>>4)<<2)
  __shared__ float Msm[16][2 * ED];      // M tile, channel-duplicated
  __shared__ float xcw[AH], w2s[AH];
  __shared__ float pxc[AH][5];
  __shared__ float patt[128][17];        // att0 partials [d][chgroup]

  const int s = blockIdx.y;
  const int d0 = blockIdx.x * 128;
  const int tid = threadIdx.x;

  // ---- prologue ----
  for (int i = tid; i < H4; i += 256) asv[i] = g_Amat[(size_t)s * H4 + i];
  {  // xc0 partials: nodes[s] @ a0W1x
    const int i = tid >> 2, q = tid & 3;
    const float* nod = &g_nodes[s * H + q * 64];
    const float* wcol = &a0W1[(size_t)(ED + q * 64) * AH + i];
    float acc = 0.f;
#pragma unroll 8
    for (int k = 0; k < 64; k++) acc += nod[k] * wcol[k * AH];
    pxc[i][q] = acc;
  }
  if (tid < 128) {  // cb0 partials: egb2 @ a0W1e  (staged in patt scratch)
    const int i = tid >> 1, q = tid & 1;
    const float* eb = &egb2[q * 64];
    const float* wcol = &a0W1[(size_t)(q * 64) * AH + i];
    float acc = 0.f;
#pragma unroll 8
    for (int k = 0; k < 64; k++) acc += eb[k] * wcol[k * AH];
    patt[i][q] = acc;
  }
  __syncthreads();
  if (tid < AH) {
    xcw[tid] = pxc[tid][0] + pxc[tid][1] + pxc[tid][2] + pxc[tid][3] +
               patt[tid][0] + patt[tid][1] + a0b1[tid];
    w2s[tid] = a0W2[tid];
  }

  // ---- main loop coords ----
  const int sdd = tid >> 1;                       // staging d 0..127
  const int skh = (tid & 1) * 8;                  // staging k base
  const int scol = sdd + ((sdd >> 4) << 2);
  const float* bsrc = &g_Bmat[(size_t)(d0 + sdd) * H4];

  const int dt = (tid & 7) * 16;                  // compute d base
  const int acol = dt + ((dt >> 4) << 2);
  const int ct = (tid >> 3) * 4;                  // compute ch base 0..124
  unsigned long long acc[8][4] = {};              // [d-pair][ch], packed over d

  for (int tile = 0; tile < 64; tile++) {
    const int k0 = tile * 16;
    // issue global loads before the barrier (latency overlaps barrier wait)
    float4 b0 = *(const float4*)&bsrc[k0 + skh];
    float4 b1 = *(const float4*)&bsrc[k0 + skh + 4];
    float4 mreg[4];
    {
      const float4* msrc = (const float4*)&g_Mdup[(size_t)k0 * 2 * ED];
#pragma unroll
      for (int j = 0; j < 4; j++) mreg[j] = msrc[j * 256 + tid];
    }
    __syncthreads();  // previous tile consumed (and prologue done on tile 0)
    {
      const float* av = &asv[k0 + skh];
      Ts[skh + 0][scol] = fmaxf(av[0] + b0.x, 0.f);
      Ts[skh + 1][scol] = fmaxf(av[1] + b0.y, 0.f);
      Ts[skh + 2][scol] = fmaxf(av[2] + b0.z, 0.f);
      Ts[skh + 3][scol] = fmaxf(av[3] + b0.w, 0.f);
      Ts[skh + 4][scol] = fmaxf(av[4] + b1.x, 0.f);
      Ts[skh + 5][scol] = fmaxf(av[5] + b1.y, 0.f);
      Ts[skh + 6][scol] = fmaxf(av[6] + b1.z, 0.f);
      Ts[skh + 7][scol] = fmaxf(av[7] + b1.w, 0.f);
#pragma unroll
      for (int j = 0; j < 4; j++) ((float4*)Msm)[j * 256 + tid] = mreg[j];
    }
    __syncthreads();
#pragma unroll
    for (int k = 0; k < 16; k++) {
      ulonglong2 a01 = *(const ulonglong2*)&Ts[k][acol];
      ulonglong2 a23 = *(const ulonglong2*)&Ts[k][acol + 4];
      ulonglong2 a45 = *(const ulonglong2*)&Ts[k][acol + 8];
      ulonglong2 a67 = *(const ulonglong2*)&Ts[k][acol + 12];
      unsigned long long m0 = *(const unsigned long long*)&Msm[k][2 * ct];
      unsigned long long m1 = *(const unsigned long long*)&Msm[k][2 * ct + 2];
      unsigned long long m2 = *(const unsigned long long*)&Msm[k][2 * ct + 4];
      unsigned long long m3 = *(const unsigned long long*)&Msm[k][2 * ct + 6];
      ffma2(acc[0][0], a01.x, m0); ffma2(acc[0][1], a01.x, m1);
      ffma2(acc[0][2], a01.x, m2); ffma2(acc[0][3], a01.x, m3);
      ffma2(acc[1][0], a01.y, m0); ffma2(acc[1][1], a01.y, m1);
      ffma2(acc[1][2], a01.y, m2); ffma2(acc[1][3], a01.y, m3);
      ffma2(acc[2][0], a23.x, m0); ffma2(acc[2][1], a23.x, m1);
      ffma2(acc[2][2], a23.x, m2); ffma2(acc[2][3], a23.x, m3);
      ffma2(acc[3][0], a23.y, m0); ffma2(acc[3][1], a23.y, m1);
      ffma2(acc[3][2], a23.y, m2); ffma2(acc[3][3], a23.y, m3);
      ffma2(acc[4][0], a45.x, m0); ffma2(acc[4][1], a45.x, m1);
      ffma2(acc[4][2], a45.x, m2); ffma2(acc[4][3], a45.x, m3);
      ffma2(acc[5][0], a45.y, m0); ffma2(acc[5][1], a45.y, m1);
      ffma2(acc[5][2], a45.y, m2); ffma2(acc[5][3], a45.y, m3);
      ffma2(acc[6][0], a67.x, m0); ffma2(acc[6][1], a67.x, m1);
      ffma2(acc[6][2], a67.x, m2); ffma2(acc[6][3], a67.x, m3);
      ffma2(acc[7][0], a67.y, m0); ffma2(acc[7][1], a67.y, m1);
      ffma2(acc[7][2], a67.y, m2); ffma2(acc[7][3], a67.y, m3);
    }
  }
  __syncthreads();  // main loop done; patt free for reuse

  // ---- epilogue ----
  const int ctg = tid >> 3;
  if (ct < AH) {
    float s16[16];
#pragma unroll
    for (int dp = 0; dp < 8; dp++) {
      float2 v0 = up2(acc[dp][0]), v1 = up2(acc[dp][1]);
      float2 v2 = up2(acc[dp][2]), v3 = up2(acc[dp][3]);
      s16[2 * dp] = fmaxf(v0.x + xcw[ct], 0.f) * w2s[ct] +
                    fmaxf(v1.x + xcw[ct + 1], 0.f) * w2s[ct + 1] +
                    fmaxf(v2.x + xcw[ct + 2], 0.f) * w2s[ct + 2] +
                    fmaxf(v3.x + xcw[ct + 3], 0.f) * w2s[ct + 3];
      s16[2 * dp + 1] = fmaxf(v0.y + xcw[ct], 0.f) * w2s[ct] +
                        fmaxf(v1.y + xcw[ct + 1], 0.f) * w2s[ct + 1] +
                        fmaxf(v2.y + xcw[ct + 2], 0.f) * w2s[ct + 2] +
                        fmaxf(v3.y + xcw[ct + 3], 0.f) * w2s[ct + 3];
    }
#pragma unroll
    for (int j = 0; j < 16; j++) patt[dt + j][ctg] = s16[j];
  } else {
    const int chb = ct - AH;
#pragma unroll
    for (int dp = 0; dp < 8; dp++) {
      float2 v0 = up2(acc[dp][0]), v1 = up2(acc[dp][1]);
      float2 v2 = up2(acc[dp][2]), v3 = up2(acc[dp][3]);
      float4 o0 = make_float4(v0.x, v1.x, v2.x, v3.x);
      float4 o1 = make_float4(v0.y, v1.y, v2.y, v3.y);
      const size_t base = ((size_t)s * N_NODES + d0 + dt + 2 * dp) * AH + chb;
      *(float4*)&g_hid1[base] = o0;
      *(float4*)&g_hid1[base + AH] = o1;
    }
  }
  __syncthreads();
  if (tid < 128) {
    float v = 0.f;
#pragma unroll
    for (int g = 0; g < 16; g++) v += patt[tid][g];
    float att =
        (d0 + tid == s) ? 0.f : 1.f / (1.f + expf(-(v + a0b2[0])));
    g_Att0T[(size_t)(d0 + tid) * N_NODES + s] = att;
  }
}

// ------------------ attention layer 1 row-sums w[s] -------------------------
__global__ void att1w_kernel(const float* __restrict__ a1W1,
                             const float* __restrict__ a1b1,
                             const float* __restrict__ a1W2,
                             const float* __restrict__ a1b2,
                             const float* __restrict__ egb2) {
  const int s = blockIdx.x;
  const int warp = threadIdx.x >> 5, lane = threadIdx.x & 31;
  __shared__ float pxc[AH][5];
  __shared__ float pcb[AH][3];
  __shared__ float xc[AH], w2[AH];
  __shared__ float wsum[8];
  {  // xc1 partials: x1[s] @ a1W1x
    const int i = threadIdx.x >> 2, q = threadIdx.x & 3;
    const float* xs = &g_x1[s * H + q * 64];
    const float* wcol = &a1W1[(size_t)(ED + q * 64) * AH + i];
    float acc = 0.f;
#pragma unroll 8
    for (int k = 0; k < 64; k++) acc += xs[k] * wcol[k * AH];
    pxc[i][q] = acc;
  }
  if (threadIdx.x < 128) {  // cb1 partials: egb2 @ a1W1e
    const int i = threadIdx.x >> 1, q = threadIdx.x & 1;
    const float* eb = &egb2[q * 64];
    const float* wcol = &a1W1[(size_t)(q * 64) * AH + i];
    float acc = 0.f;
#pragma unroll 8
    for (int k = 0; k < 64; k++) acc += eb[k] * wcol[k * AH];
    pcb[i][q] = acc;
  }
  __syncthreads();
  if (threadIdx.x < AH) {
    xc[threadIdx.x] = pxc[threadIdx.x][0] + pxc[threadIdx.x][1] +
                      pxc[threadIdx.x][2] + pxc[threadIdx.x][3] +
                      pcb[threadIdx.x][0] + pcb[threadIdx.x][1] +
                      a1b1[threadIdx.x];
    w2[threadIdx.x] = a1W2[threadIdx.x];
  }
  __syncthreads();
  const float b2 = a1b2[0];
  float accv = 0.f;
  for (int d = warp; d < N_NODES; d += 8) {
    float2 h2 = *(const float2*)&g_hid1[(((size_t)s) * N_NODES + d) * AH + lane * 2];
    float v = fmaxf(h2.x + xc[lane * 2], 0.f) * w2[lane * 2] +
              fmaxf(h2.y + xc[lane * 2 + 1], 0.f) * w2[lane * 2 + 1];
    for (int o = 16; o > 0; o >>= 1) v += __shfl_down_sync(0xffffffffu, v, o);
    if (lane == 0 && d != s) accv += 1.f / (1.f + expf(-(v + b2)));
  }
  if (lane == 0) wsum[warp] = accv;
  __syncthreads();
  if (threadIdx.x == 0) {
    float t = 0.f;
    for (int i = 0; i < 8; i++) t += wsum[i];
    g_w[s] = t;
  }
}

// --------------------------- final reduction --------------------------------
__global__ void final_kernel(const float* __restrict__ c1W,
                             const float* __restrict__ c1b,
                             float* __restrict__ out) {
  __shared__ float v[H];
  __shared__ float wsh[N_NODES];
  const int tid = threadIdx.x;  // 256
  for (int i = tid; i < N_NODES; i += blockDim.x) wsh[i] = g_w[i];
  __syncthreads();
  float s = 0.f;
  for (int n = 0; n < N_NODES; n++) s += wsh[n] * g_x1[n * H + tid];
  v[tid] = s;
  __syncthreads();
  float o = (float)N_NODES * c1b[tid];
  for (int h = 0; h < H; h++) o += v[h] * c1W[h * H + tid];
  out[tid] = o;
}

// ------------------------------- launcher -----------------------------------
static float* sym_addr(const void* symbol) {
  void* p = nullptr;
  cudaGetSymbolAddress(&p, symbol);
  return (float*)p;
}

extern "C" void kernel_launch(void* const* d_in, const int* in_sizes, int n_in,
                              void* d_out, int out_size) {
  const float* z = (const float*)d_in[0];
  const float* Wih = (const float*)d_in[1];
  const float* Whh = (const float*)d_in[2];
  const float* bih = (const float*)d_in[3];
  const float* bhh = (const float*)d_in[4];
  const float* egW1 = (const float*)d_in[5];
  const float* egb1 = (const float*)d_in[6];
  const float* egW2 = (const float*)d_in[7];
  const float* egb2 = (const float*)d_in[8];
  const float* a0W1 = (const float*)d_in[9];
  const float* a0b1 = (const float*)d_in[10];
  const float* a0W2 = (const float*)d_in[11];
  const float* a0b2 = (const float*)d_in[12];
  const float* a1W1 = (const float*)d_in[13];
  const float* a1b1 = (const float*)d_in[14];
  const float* a1W2 = (const float*)d_in[15];
  const float* a1b2 = (const float*)d_in[16];
  const float* c0W = (const float*)d_in[17];
  const float* c0b = (const float*)d_in[18];
  const float* c1W = (const float*)d_in[19];
  const float* c1b = (const float*)d_in[20];
  float* out = (float*)d_out;

  float* nodes = sym_addr(g_nodes);
  float* Amat = sym_addr(g_Amat);
  float* Bmat = sym_addr(g_Bmat);
  float* Mdup = sym_addr(g_Mdup);
  float* Att0T = sym_addr(g_Att0T);
  float* agg0 = sym_addr(g_agg0);
  float* x1 = sym_addr(g_x1);

  // 0: GRU -> nodes
  gru_kernel<<<GRU_CTAS, 384>>>(z, Wih, Whh, bih, bhh);

  // 1: A = nodes@W1a + eg_b1 ; B = nodes@W1b
  gemm_dual_kernel<false><<<dim3(H4 / 64, N_NODES / 64, 2), 256>>>(
      N_NODES, H4, H, nodes, H, egW1, egW1 + (size_t)H * H4, H4, egb1, Amat,
      Bmat, H4);

  // 2: Mdup = dup(eg_W2 @ [a0W1e | a1W1e])
  gemm_dual_kernel<true><<<dim3(1, H4 / 64, 2), 256>>>(
      H4, AH, ED, egW2, ED, a0W1, a1W1, AH, nullptr, Mdup, Mdup + 2 * AH, 2 * ED);

  // 3: edge GEMM (f32x2) + fused att0 -> g_Att0T, g_hid1
  edge_kernel<<<dim3(N_NODES / 128, N_NODES), 256>>>(a0W1, a0b1, a0W2, a0b2,
                                                     egb2);

  // 4-5: agg0 = Att0T @ nodes ; x1 = relu(agg0 @ c0W + c0b)
  gemm_kernel<false><<<dim3(H / 64, N_NODES / 64), 256>>>(
      N_NODES, H, N_NODES, Att0T, N_NODES, nodes, H, nullptr, agg0, H);
  gemm_kernel<true><<<dim3(H / 64, N_NODES / 64), 256>>>(
      N_NODES, H, H, agg0, H, c0W, H, c0b, x1, H);

  // 6: w[s] = sum_d att1(s,d)  (xc1+cb1 inline)
  att1w_kernel<<<N_NODES, 256>>>(a1W1, a1b1, a1W2, a1b2, egb2);

  // 7: out = (sum_s w[s] x1[s]) @ c1W + 384*c1b
  final_kernel<<<1, H>>>(c1W, c1b, out);
}

// round 9
// speedup vs baseline: 1.6347x; 1.1204x over previous
#include <cuda_runtime.h>
#include <cooperative_groups.h>
#include <math.h>
#include <stdint.h>

namespace cg = cooperative_groups;

#define N_NODES 384
#define H 256
#define Z 128
#define ED 128
#define AH 64
#define H4 1024
#define NE (N_NODES * N_NODES)

// ------------------------- scratch (device globals) -------------------------
__device__ float g_nodes[N_NODES * H];       // [384,256]
__device__ float g_Amat[N_NODES * H4];       // nodes@W1a + eg_b1
__device__ float g_Bmat[N_NODES * H4];       // nodes@W1b
__device__ float g_M[H4 * ED];               // egW2@[a0W1e|a1W1e]  [1024,128]
__device__ float g_hid1[(size_t)NE * AH];    // att1 half of hidden, [s][d][64]
__device__ float g_Att0T[NE];                // att0 matrix, [d][s]
__device__ float g_agg0[N_NODES * H];
__device__ float g_x1[N_NODES * H];
__device__ float g_w[N_NODES];

// --------------------------- packed f32x2 helpers ---------------------------
__device__ __forceinline__ void ffma2(unsigned long long& acc,
                                      unsigned long long a,
                                      unsigned long long b) {
  asm("fma.rn.f32x2 %0, %1, %2, %0;" : "+l"(acc) : "l"(a), "l"(b));
}
__device__ __forceinline__ float2 up2(unsigned long long v) {
  float2 r;
  r.x = __uint_as_float((unsigned)(v & 0xffffffffull));
  r.y = __uint_as_float((unsigned)(v >> 32));
  return r;
}
__device__ __forceinline__ unsigned long long dup2(float f) {
  unsigned long long r;
  asm("mov.b64 %0, {%1, %1};" : "=l"(r) : "f"(f));
  return r;
}

// ------------------------------- GRU kernel ---------------------------------
// 8-CTA cluster, 384 threads. Whh register-resident: warp w, lane l handles
// row r=(w%3)*32+l (gate g=w%3, idx l), k-quarter kq=w/3 (64 k, 32 packed regs).
#define GRU_CTAS 8
#define GRU_HPC 32
#define GRU_ROWS 96

__global__ void __cluster_dims__(GRU_CTAS, 1, 1) __launch_bounds__(384)
gru_kernel(const float* __restrict__ z, const float* __restrict__ Wih,
           const float* __restrict__ Whh, const float* __restrict__ bih,
           const float* __restrict__ bhh) {
  __shared__ float hbuf[2][H];
  __shared__ float part[4 * GRU_ROWS];
  __shared__ float gi[GRU_ROWS];
  __shared__ float bh[GRU_ROWS];
  cg::cluster_group cluster = cg::this_cluster();
  const int c = cluster.block_rank();
  const int tid = threadIdx.x;
  const int w = tid >> 5, l = tid & 31;
  const int gate = w % 3, kq = w / 3;
  const int r = gate * 32 + l;
  const int grow = gate * H + c * GRU_HPC + l;

  unsigned long long wr[32];
  {
    const float* wsrc = &Whh[(size_t)grow * H + kq * 64];
#pragma unroll
    for (int j = 0; j < 16; j++) {
      ulonglong2 t = *(const ulonglong2*)&wsrc[j * 4];
      wr[2 * j] = t.x;
      wr[2 * j + 1] = t.y;
    }
  }
  for (int rr = tid; rr < GRU_ROWS; rr += 384) {
    int g2 = rr >> 5, i2 = rr & 31;
    int gr = g2 * H + c * GRU_HPC + i2;
    float s = bih[gr];
    for (int k = 0; k < Z; k++) s += Wih[gr * Z + k] * z[k];
    gi[rr] = s;
    bh[rr] = bhh[gr];
  }
  for (int k = tid; k < 2 * H; k += 384) hbuf[0][k] = 0.f;
  __syncthreads();
  cluster.sync();

  for (int step = 0; step < N_NODES; step++) {
    const int cur = step & 1, nxt = cur ^ 1;
    {
      const float* hsrc = &hbuf[cur][kq * 64];
      unsigned long long a0 = 0, a1 = 0, a2 = 0, a3 = 0;
#pragma unroll
      for (int j = 0; j < 16; j += 2) {
        ulonglong2 hv0 = *(const ulonglong2*)&hsrc[j * 4];
        ulonglong2 hv1 = *(const ulonglong2*)&hsrc[j * 4 + 4];
        ffma2(a0, wr[2 * j], hv0.x);
        ffma2(a1, wr[2 * j + 1], hv0.y);
        ffma2(a2, wr[2 * j + 2], hv1.x);
        ffma2(a3, wr[2 * j + 3], hv1.y);
      }
      float2 s0 = up2(a0), s1 = up2(a1), s2 = up2(a2), s3 = up2(a3);
      part[kq * GRU_ROWS + r] =
          ((s0.x + s0.y) + (s1.x + s1.y)) + ((s2.x + s2.y) + (s3.x + s3.y));
    }
    __syncthreads();
    if (tid < GRU_HPC) {
      const int i = tid;
      float ghr = part[i] + part[96 + i] + part[192 + i] + part[288 + i] + bh[i];
      float ghz = part[32 + i] + part[96 + 32 + i] + part[192 + 32 + i] +
                  part[288 + 32 + i] + bh[32 + i];
      float ghn = part[64 + i] + part[96 + 64 + i] + part[192 + 64 + i] +
                  part[288 + 64 + i] + bh[64 + i];
      float rg = 1.f / (1.f + expf(-(gi[i] + ghr)));
      float ug = 1.f / (1.f + expf(-(gi[32 + i] + ghz)));
      float ng = tanhf(gi[64 + i] + rg * ghn);
      float h2 = (1.f - ug) * ng + ug * hbuf[cur][c * GRU_HPC + i];
      g_nodes[step * H + c * GRU_HPC + i] = h2;
#pragma unroll
      for (int rk = 0; rk < GRU_CTAS; rk++) {
        float* remote = (float*)cluster.map_shared_rank(hbuf, rk);
        remote[nxt * H + c * GRU_HPC + i] = h2;
      }
    }
    cluster.sync();
  }
}

// --------------------------- generic fp32 GEMM ------------------------------
template <bool RELU>
__global__ void gemm_kernel(int M, int N, int K, const float* __restrict__ A,
                            int lda, const float* __restrict__ B, int ldb,
                            const float* __restrict__ bias,
                            float* __restrict__ C, int ldc) {
  __shared__ float As[16][68];
  __shared__ float Bs[16][68];
  const int tx = threadIdx.x % 16, ty = threadIdx.x / 16;
  const int m0 = blockIdx.y * 64, n0 = blockIdx.x * 64;
  float acc[4][4] = {};
  for (int k0 = 0; k0 < K; k0 += 16) {
    for (int idx = threadIdx.x; idx < 64 * 16; idx += 256) {
      int m = idx / 16, k = idx % 16;
      As[k][m] = A[(size_t)(m0 + m) * lda + k0 + k];
    }
    for (int idx = threadIdx.x; idx < 16 * 64; idx += 256) {
      int k = idx / 64, n = idx % 64;
      Bs[k][n] = B[(size_t)(k0 + k) * ldb + n0 + n];
    }
    __syncthreads();
#pragma unroll
    for (int k = 0; k < 16; k++) {
      float a[4], b[4];
#pragma unroll
      for (int i = 0; i < 4; i++) a[i] = As[k][ty * 4 + i];
#pragma unroll
      for (int j = 0; j < 4; j++) b[j] = Bs[k][tx * 4 + j];
#pragma unroll
      for (int i = 0; i < 4; i++)
#pragma unroll
        for (int j = 0; j < 4; j++) acc[i][j] += a[i] * b[j];
    }
    __syncthreads();
  }
#pragma unroll
  for (int i = 0; i < 4; i++) {
#pragma unroll
    for (int j = 0; j < 4; j++) {
      float v = acc[i][j] + (bias ? bias[n0 + tx * 4 + j] : 0.f);
      if (RELU) v = fmaxf(v, 0.f);
      C[(size_t)(m0 + ty * 4 + i) * ldc + n0 + tx * 4 + j] = v;
    }
  }
}

// ---------------- dual GEMM: blockIdx.z selects (B, C, bias) ----------------
__global__ void gemm_dual_kernel(int M, int N, int K, const float* __restrict__ A,
                                 int lda, const float* __restrict__ B0,
                                 const float* __restrict__ B1, int ldb,
                                 const float* __restrict__ bias0,
                                 float* __restrict__ C0, float* __restrict__ C1,
                                 int ldc) {
  const float* B = blockIdx.z ? B1 : B0;
  float* C = blockIdx.z ? C1 : C0;
  const float* bias = blockIdx.z ? nullptr : bias0;
  __shared__ float As[16][68];
  __shared__ float Bs[16][68];
  const int tx = threadIdx.x % 16, ty = threadIdx.x / 16;
  const int m0 = blockIdx.y * 64, n0 = blockIdx.x * 64;
  float acc[4][4] = {};
  for (int k0 = 0; k0 < K; k0 += 16) {
    for (int idx = threadIdx.x; idx < 64 * 16; idx += 256) {
      int m = idx / 16, k = idx % 16;
      As[k][m] = A[(size_t)(m0 + m) * lda + k0 + k];
    }
    for (int idx = threadIdx.x; idx < 16 * 64; idx += 256) {
      int k = idx / 64, n = idx % 64;
      Bs[k][n] = B[(size_t)(k0 + k) * ldb + n0 + n];
    }
    __syncthreads();
#pragma unroll
    for (int k = 0; k < 16; k++) {
      float a[4], b[4];
#pragma unroll
      for (int i = 0; i < 4; i++) a[i] = As[k][ty * 4 + i];
#pragma unroll
      for (int j = 0; j < 4; j++) b[j] = Bs[k][tx * 4 + j];
#pragma unroll
      for (int i = 0; i < 4; i++)
#pragma unroll
        for (int j = 0; j < 4; j++) acc[i][j] += a[i] * b[j];
    }
    __syncthreads();
  }
#pragma unroll
  for (int i = 0; i < 4; i++) {
#pragma unroll
    for (int j = 0; j < 4; j++) {
      float v = acc[i][j] + (bias ? bias[n0 + tx * 4 + j] : 0.f);
      C[(size_t)(m0 + ty * 4 + i) * ldc + n0 + tx * 4 + j] = v;
    }
  }
}

// ------------------- f32x2 edge GEMM + fused attention-0 --------------------
// Per CTA: s = blockIdx.y, d-tile [d0,d0+128), all 128 ch. 256 threads.
// Thread tile 8d x 8ch, packed over d; M packs built in registers (no dup).
// Skew col(d) = d + (d>>3)*4 -> the 16 distinct 32B A-blocks per warp map
// 2-per-bank-group (minimal 2 wavefronts per LDS.128).
#define ETS_LD 192

__global__ void __launch_bounds__(256, 2) edge_kernel(
    const float* __restrict__ a0W1, const float* __restrict__ a0b1,
    const float* __restrict__ a0W2, const float* __restrict__ a0b2,
    const float* __restrict__ egb2) {
  __shared__ float asv[H4];
  __shared__ float Ts[16][ETS_LD];       // T tile, skewed
  __shared__ float Msm[16][ED];          // M tile, natural layout
  __shared__ float xcw[AH], w2s[AH];
  __shared__ float pxc[AH][5];
  __shared__ float patt[128][9];         // att0 partials [d][chgroup]

  const int s = blockIdx.y;
  const int d0 = blockIdx.x * 128;
  const int tid = threadIdx.x;

  // ---- prologue ----
  for (int i = tid; i < H4; i += 256) asv[i] = g_Amat[(size_t)s * H4 + i];
  {  // xc0 partials: nodes[s] @ a0W1x
    const int i = tid >> 2, q = tid & 3;
    const float* nod = &g_nodes[s * H + q * 64];
    const float* wcol = &a0W1[(size_t)(ED + q * 64) * AH + i];
    float acc = 0.f;
#pragma unroll 8
    for (int k = 0; k < 64; k++) acc += nod[k] * wcol[k * AH];
    pxc[i][q] = acc;
  }
  if (tid < 128) {  // cb0 partials: egb2 @ a0W1e (staged in patt scratch)
    const int i = tid >> 1, q = tid & 1;
    const float* eb = &egb2[q * 64];
    const float* wcol = &a0W1[(size_t)(q * 64) * AH + i];
    float acc = 0.f;
#pragma unroll 8
    for (int k = 0; k < 64; k++) acc += eb[k] * wcol[k * AH];
    patt[i][q] = acc;
  }
  __syncthreads();
  if (tid < AH) {
    xcw[tid] = pxc[tid][0] + pxc[tid][1] + pxc[tid][2] + pxc[tid][3] +
               patt[tid][0] + patt[tid][1] + a0b1[tid];
    w2s[tid] = a0W2[tid];
  }

  // ---- main loop coords ----
  const int sdd = tid >> 1;                       // staging d 0..127
  const int skh = (tid & 1) * 8;                  // staging k base
  const int scol = sdd + ((sdd >> 3) << 2);
  const float* bsrc = &g_Bmat[(size_t)(d0 + sdd) * H4];

  const int dt = (tid & 15) * 8;                  // compute d base (8 d)
  const int acol = dt + ((dt >> 3) << 2);
  const int ct = (tid >> 4) * 8;                  // compute ch base (8 ch)
  unsigned long long acc[4][8] = {};              // [d-pair][ch]

  for (int tile = 0; tile < 64; tile++) {
    const int k0 = tile * 16;
    // global loads issued before the barrier (latency overlaps barrier wait)
    float4 b0 = *(const float4*)&bsrc[k0 + skh];
    float4 b1 = *(const float4*)&bsrc[k0 + skh + 4];
    float4 mr0, mr1;
    {
      const float4* msrc = (const float4*)&g_M[(size_t)k0 * ED];
      mr0 = msrc[tid];
      mr1 = msrc[256 + tid];
    }
    __syncthreads();  // previous tile consumed (and prologue done on tile 0)
    {
      const float* av = &asv[k0 + skh];
      Ts[skh + 0][scol] = fmaxf(av[0] + b0.x, 0.f);
      Ts[skh + 1][scol] = fmaxf(av[1] + b0.y, 0.f);
      Ts[skh + 2][scol] = fmaxf(av[2] + b0.z, 0.f);
      Ts[skh + 3][scol] = fmaxf(av[3] + b0.w, 0.f);
      Ts[skh + 4][scol] = fmaxf(av[4] + b1.x, 0.f);
      Ts[skh + 5][scol] = fmaxf(av[5] + b1.y, 0.f);
      Ts[skh + 6][scol] = fmaxf(av[6] + b1.z, 0.f);
      Ts[skh + 7][scol] = fmaxf(av[7] + b1.w, 0.f);
      ((float4*)Msm)[tid] = mr0;
      ((float4*)Msm)[256 + tid] = mr1;
    }
    __syncthreads();
#pragma unroll
    for (int k = 0; k < 16; k++) {
      ulonglong2 aA = *(const ulonglong2*)&Ts[k][acol];       // d 0..3
      ulonglong2 aB = *(const ulonglong2*)&Ts[k][acol + 4];   // d 4..7
      float4 m0 = *(const float4*)&Msm[k][ct];
      float4 m1 = *(const float4*)&Msm[k][ct + 4];
      const float mv[8] = {m0.x, m0.y, m0.z, m0.w, m1.x, m1.y, m1.z, m1.w};
#pragma unroll
      for (int c = 0; c < 8; c++) {
        const unsigned long long mm = dup2(mv[c]);
        ffma2(acc[0][c], aA.x, mm);
        ffma2(acc[1][c], aA.y, mm);
        ffma2(acc[2][c], aB.x, mm);
        ffma2(acc[3][c], aB.y, mm);
      }
    }
  }
  __syncthreads();  // main loop done; patt free for reuse

  // ---- epilogue ----
  const int ctg = tid >> 4;  // 0..15
  if (ct < AH) {
    // att0 half: per d, partial sum over this thread's 8 channels
#pragma unroll
    for (int p = 0; p < 4; p++) {
      float se = 0.f, so = 0.f;
#pragma unroll
      for (int c = 0; c < 8; c++) {
        float2 v = up2(acc[p][c]);
        se += fmaxf(v.x + xcw[ct + c], 0.f) * w2s[ct + c];
        so += fmaxf(v.y + xcw[ct + c], 0.f) * w2s[ct + c];
      }
      patt[dt + 2 * p][ctg] = se;
      patt[dt + 2 * p + 1][ctg] = so;
    }
  } else {
    const int chb = ct - AH;
#pragma unroll
    for (int p = 0; p < 4; p++) {
      float2 v0 = up2(acc[p][0]), v1 = up2(acc[p][1]);
      float2 v2 = up2(acc[p][2]), v3 = up2(acc[p][3]);
      float2 v4 = up2(acc[p][4]), v5 = up2(acc[p][5]);
      float2 v6 = up2(acc[p][6]), v7 = up2(acc[p][7]);
      const size_t base =
          ((size_t)s * N_NODES + d0 + dt + 2 * p) * AH + chb;
      *(float4*)&g_hid1[base] = make_float4(v0.x, v1.x, v2.x, v3.x);
      *(float4*)&g_hid1[base + 4] = make_float4(v4.x, v5.x, v6.x, v7.x);
      *(float4*)&g_hid1[base + AH] = make_float4(v0.y, v1.y, v2.y, v3.y);
      *(float4*)&g_hid1[base + AH + 4] = make_float4(v4.y, v5.y, v6.y, v7.y);
    }
  }
  __syncthreads();
  if (tid < 128) {
    float v = 0.f;
#pragma unroll
    for (int g = 0; g < 8; g++) v += patt[tid][g];
    float att = (d0 + tid == s) ? 0.f : 1.f / (1.f + expf(-(v + a0b2[0])));
    g_Att0T[(size_t)(d0 + tid) * N_NODES + s] = att;
  }
}

// ------------------ attention layer 1 row-sums w[s] -------------------------
__global__ void att1w_kernel(const float* __restrict__ a1W1,
                             const float* __restrict__ a1b1,
                             const float* __restrict__ a1W2,
                             const float* __restrict__ a1b2,
                             const float* __restrict__ egb2) {
  const int s = blockIdx.x;
  const int warp = threadIdx.x >> 5, lane = threadIdx.x & 31;
  __shared__ float pxc[AH][5];
  __shared__ float pcb[AH][3];
  __shared__ float xc[AH], w2[AH];
  __shared__ float wsum[8];
  {  // xc1 partials: x1[s] @ a1W1x
    const int i = threadIdx.x >> 2, q = threadIdx.x & 3;
    const float* xs = &g_x1[s * H + q * 64];
    const float* wcol = &a1W1[(size_t)(ED + q * 64) * AH + i];
    float acc = 0.f;
#pragma unroll 8
    for (int k = 0; k < 64; k++) acc += xs[k] * wcol[k * AH];
    pxc[i][q] = acc;
  }
  if (threadIdx.x < 128) {  // cb1 partials: egb2 @ a1W1e
    const int i = threadIdx.x >> 1, q = threadIdx.x & 1;
    const float* eb = &egb2[q * 64];
    const float* wcol = &a1W1[(size_t)(q * 64) * AH + i];
    float acc = 0.f;
#pragma unroll 8
    for (int k = 0; k < 64; k++) acc += eb[k] * wcol[k * AH];
    pcb[i][q] = acc;
  }
  __syncthreads();
  if (threadIdx.x < AH) {
    xc[threadIdx.x] = pxc[threadIdx.x][0] + pxc[threadIdx.x][1] +
                      pxc[threadIdx.x][2] + pxc[threadIdx.x][3] +
                      pcb[threadIdx.x][0] + pcb[threadIdx.x][1] +
                      a1b1[threadIdx.x];
    w2[threadIdx.x] = a1W2[threadIdx.x];
  }
  __syncthreads();
  const float b2 = a1b2[0];
  float accv = 0.f;
  for (int d = warp; d < N_NODES; d += 8) {
    float2 h2 = *(const float2*)&g_hid1[(((size_t)s) * N_NODES + d) * AH + lane * 2];
    float v = fmaxf(h2.x + xc[lane * 2], 0.f) * w2[lane * 2] +
              fmaxf(h2.y + xc[lane * 2 + 1], 0.f) * w2[lane * 2 + 1];
    for (int o = 16; o > 0; o >>= 1) v += __shfl_down_sync(0xffffffffu, v, o);
    if (lane == 0 && d != s) accv += 1.f / (1.f + expf(-(v + b2)));
  }
  if (lane == 0) wsum[warp] = accv;
  __syncthreads();
  if (threadIdx.x == 0) {
    float t = 0.f;
    for (int i = 0; i < 8; i++) t += wsum[i];
    g_w[s] = t;
  }
}

// --------------------------- final reduction --------------------------------
__global__ void final_kernel(const float* __restrict__ c1W,
                             const float* __restrict__ c1b,
                             float* __restrict__ out) {
  __shared__ float v[H];
  __shared__ float wsh[N_NODES];
  const int tid = threadIdx.x;  // 256
  for (int i = tid; i < N_NODES; i += blockDim.x) wsh[i] = g_w[i];
  __syncthreads();
  float s = 0.f;
  for (int n = 0; n < N_NODES; n++) s += wsh[n] * g_x1[n * H + tid];
  v[tid] = s;
  __syncthreads();
  float o = (float)N_NODES * c1b[tid];
  for (int h = 0; h < H; h++) o += v[h] * c1W[h * H + tid];
  out[tid] = o;
}

// ------------------------------- launcher -----------------------------------
static float* sym_addr(const void* symbol) {
  void* p = nullptr;
  cudaGetSymbolAddress(&p, symbol);
  return (float*)p;
}

extern "C" void kernel_launch(void* const* d_in, const int* in_sizes, int n_in,
                              void* d_out, int out_size) {
  const float* z = (const float*)d_in[0];
  const float* Wih = (const float*)d_in[1];
  const float* Whh = (const float*)d_in[2];
  const float* bih = (const float*)d_in[3];
  const float* bhh = (const float*)d_in[4];
  const float* egW1 = (const float*)d_in[5];
  const float* egb1 = (const float*)d_in[6];
  const float* egW2 = (const float*)d_in[7];
  const float* egb2 = (const float*)d_in[8];
  const float* a0W1 = (const float*)d_in[9];
  const float* a0b1 = (const float*)d_in[10];
  const float* a0W2 = (const float*)d_in[11];
  const float* a0b2 = (const float*)d_in[12];
  const float* a1W1 = (const float*)d_in[13];
  const float* a1b1 = (const float*)d_in[14];
  const float* a1W2 = (const float*)d_in[15];
  const float* a1b2 = (const float*)d_in[16];
  const float* c0W = (const float*)d_in[17];
  const float* c0b = (const float*)d_in[18];
  const float* c1W = (const float*)d_in[19];
  const float* c1b = (const float*)d_in[20];
  float* out = (float*)d_out;

  float* nodes = sym_addr(g_nodes);
  float* Amat = sym_addr(g_Amat);
  float* Bmat = sym_addr(g_Bmat);
  float* Mmat = sym_addr(g_M);
  float* Att0T = sym_addr(g_Att0T);
  float* agg0 = sym_addr(g_agg0);
  float* x1 = sym_addr(g_x1);

  // 0: GRU -> nodes
  gru_kernel<<<GRU_CTAS, 384>>>(z, Wih, Whh, bih, bhh);

  // 1: A = nodes@W1a + eg_b1 ; B = nodes@W1b
  gemm_dual_kernel<<<dim3(H4 / 64, N_NODES / 64, 2), 256>>>(
      N_NODES, H4, H, nodes, H, egW1, egW1 + (size_t)H * H4, H4, egb1, Amat,
      Bmat, H4);

  // 2: M = eg_W2 @ [a0W1e | a1W1e]
  gemm_dual_kernel<<<dim3(1, H4 / 64, 2), 256>>>(
      H4, AH, ED, egW2, ED, a0W1, a1W1, AH, nullptr, Mmat, Mmat + AH, ED);

  // 3: edge GEMM (f32x2, 8d x 8ch, reg-packed M) + fused att0
  edge_kernel<<<dim3(N_NODES / 128, N_NODES), 256>>>(a0W1, a0b1, a0W2, a0b2,
                                                     egb2);

  // 4-5: agg0 = Att0T @ nodes ; x1 = relu(agg0 @ c0W + c0b)
  gemm_kernel<false><<<dim3(H / 64, N_NODES / 64), 256>>>(
      N_NODES, H, N_NODES, Att0T, N_NODES, nodes, H, nullptr, agg0, H);
  gemm_kernel<true><<<dim3(H / 64, N_NODES / 64), 256>>>(
      N_NODES, H, H, agg0, H, c0W, H, c0b, x1, H);

  // 6: w[s] = sum_d att1(s,d)  (xc1+cb1 inline)
  att1w_kernel<<<N_NODES, 256>>>(a1W1, a1b1, a1W2, a1b2, egb2);

  // 7: out = (sum_s w[s] x1[s]) @ c1W + 384*c1b
  final_kernel<<<1, H>>>(c1W, c1b, out);
}

// round 10
// speedup vs baseline: 1.7246x; 1.0550x over previous
#include <cuda_runtime.h>
#include <cooperative_groups.h>
#include <math.h>
#include <stdint.h>

namespace cg = cooperative_groups;

#define N_NODES 384
#define H 256
#define Z 128
#define ED 128
#define AH 64
#define H4 1024
#define NE (N_NODES * N_NODES)

// ------------------------- scratch (device globals) -------------------------
__device__ float g_nodes[N_NODES * H];       // [384,256]
__device__ float g_Amat[N_NODES * H4];       // nodes@W1a + eg_b1
__device__ float g_Bmat[N_NODES * H4];       // nodes@W1b
__device__ float g_M[H4 * ED];               // egW2@[a0W1e|a1W1e]  [1024,128]
__device__ float g_cb0[AH];                  // egb2@a0W1e + a0b1
__device__ float g_cb1[AH];                  // egb2@a1W1e + a1b1
__device__ float g_Xc0[N_NODES * AH];        // nodes@a0W1x + cb0
__device__ float g_hid1[(size_t)NE * AH];    // att1 half of hidden, [s][d][64]
__device__ float g_Att0T[NE];                // att0 matrix, [d][s]
__device__ float g_agg0[N_NODES * H];
__device__ float g_x1[N_NODES * H];
__device__ float g_w[N_NODES];

// --------------------------- packed f32x2 helpers ---------------------------
__device__ __forceinline__ void ffma2(unsigned long long& acc,
                                      unsigned long long a,
                                      unsigned long long b) {
  asm("fma.rn.f32x2 %0, %1, %2, %0;" : "+l"(acc) : "l"(a), "l"(b));
}
__device__ __forceinline__ float2 up2(unsigned long long v) {
  float2 r;
  r.x = __uint_as_float((unsigned)(v & 0xffffffffull));
  r.y = __uint_as_float((unsigned)(v >> 32));
  return r;
}
__device__ __forceinline__ unsigned long long dup2(float f) {
  unsigned long long r;
  asm("mov.b64 %0, {%1, %1};" : "=l"(r) : "f"(f));
  return r;
}

// ------------------------------- GRU kernel ---------------------------------
// 8-CTA cluster, 384 threads. Whh register-resident: warp w, lane l handles
// row r=(w%3)*32+l (gate g=w%3, idx l), k-quarter kq=w/3 (64 k, 32 packed regs).
#define GRU_CTAS 8
#define GRU_HPC 32
#define GRU_ROWS 96

__global__ void __cluster_dims__(GRU_CTAS, 1, 1) __launch_bounds__(384)
gru_kernel(const float* __restrict__ z, const float* __restrict__ Wih,
           const float* __restrict__ Whh, const float* __restrict__ bih,
           const float* __restrict__ bhh) {
  __shared__ float hbuf[2][H];
  __shared__ float part[4 * GRU_ROWS];
  __shared__ float gi[GRU_ROWS];
  __shared__ float bh[GRU_ROWS];
  cg::cluster_group cluster = cg::this_cluster();
  const int c = cluster.block_rank();
  const int tid = threadIdx.x;
  const int w = tid >> 5, l = tid & 31;
  const int gate = w % 3, kq = w / 3;
  const int r = gate * 32 + l;
  const int grow = gate * H + c * GRU_HPC + l;

  unsigned long long wr[32];
  {
    const float* wsrc = &Whh[(size_t)grow * H + kq * 64];
#pragma unroll
    for (int j = 0; j < 16; j++) {
      ulonglong2 t = *(const ulonglong2*)&wsrc[j * 4];
      wr[2 * j] = t.x;
      wr[2 * j + 1] = t.y;
    }
  }
  for (int rr = tid; rr < GRU_ROWS; rr += 384) {
    int g2 = rr >> 5, i2 = rr & 31;
    int gr = g2 * H + c * GRU_HPC + i2;
    float s = bih[gr];
    for (int k = 0; k < Z; k++) s += Wih[gr * Z + k] * z[k];
    gi[rr] = s;
    bh[rr] = bhh[gr];
  }
  for (int k = tid; k < 2 * H; k += 384) hbuf[0][k] = 0.f;
  __syncthreads();
  cluster.sync();

  for (int step = 0; step < N_NODES; step++) {
    const int cur = step & 1, nxt = cur ^ 1;
    {
      const float* hsrc = &hbuf[cur][kq * 64];
      unsigned long long a0 = 0, a1 = 0, a2 = 0, a3 = 0;
#pragma unroll
      for (int j = 0; j < 16; j += 2) {
        ulonglong2 hv0 = *(const ulonglong2*)&hsrc[j * 4];
        ulonglong2 hv1 = *(const ulonglong2*)&hsrc[j * 4 + 4];
        ffma2(a0, wr[2 * j], hv0.x);
        ffma2(a1, wr[2 * j + 1], hv0.y);
        ffma2(a2, wr[2 * j + 2], hv1.x);
        ffma2(a3, wr[2 * j + 3], hv1.y);
      }
      float2 s0 = up2(a0), s1 = up2(a1), s2 = up2(a2), s3 = up2(a3);
      part[kq * GRU_ROWS + r] =
          ((s0.x + s0.y) + (s1.x + s1.y)) + ((s2.x + s2.y) + (s3.x + s3.y));
    }
    __syncthreads();
    if (tid < GRU_HPC) {
      const int i = tid;
      float ghr = part[i] + part[96 + i] + part[192 + i] + part[288 + i] + bh[i];
      float ghz = part[32 + i] + part[96 + 32 + i] + part[192 + 32 + i] +
                  part[288 + 32 + i] + bh[32 + i];
      float ghn = part[64 + i] + part[96 + 64 + i] + part[192 + 64 + i] +
                  part[288 + 64 + i] + bh[64 + i];
      float rg = 1.f / (1.f + expf(-(gi[i] + ghr)));
      float ug = 1.f / (1.f + expf(-(gi[32 + i] + ghz)));
      float ng = tanhf(gi[64 + i] + rg * ghn);
      float h2 = (1.f - ug) * ng + ug * hbuf[cur][c * GRU_HPC + i];
      g_nodes[step * H + c * GRU_HPC + i] = h2;
#pragma unroll
      for (int rk = 0; rk < GRU_CTAS; rk++) {
        float* remote = (float*)cluster.map_shared_rank(hbuf, rk);
        remote[nxt * H + c * GRU_HPC + i] = h2;
      }
    }
    cluster.sync();
  }
}

// --------------------------- generic fp32 GEMM ------------------------------
template <bool RELU>
__global__ void gemm_kernel(int M, int N, int K, const float* __restrict__ A,
                            int lda, const float* __restrict__ B, int ldb,
                            const float* __restrict__ bias,
                            float* __restrict__ C, int ldc) {
  __shared__ float As[16][68];
  __shared__ float Bs[16][68];
  const int tx = threadIdx.x % 16, ty = threadIdx.x / 16;
  const int m0 = blockIdx.y * 64, n0 = blockIdx.x * 64;
  float acc[4][4] = {};
  for (int k0 = 0; k0 < K; k0 += 16) {
    for (int idx = threadIdx.x; idx < 64 * 16; idx += 256) {
      int m = idx / 16, k = idx % 16;
      As[k][m] = A[(size_t)(m0 + m) * lda + k0 + k];
    }
    for (int idx = threadIdx.x; idx < 16 * 64; idx += 256) {
      int k = idx / 64, n = idx % 64;
      Bs[k][n] = B[(size_t)(k0 + k) * ldb + n0 + n];
    }
    __syncthreads();
#pragma unroll
    for (int k = 0; k < 16; k++) {
      float a[4], b[4];
#pragma unroll
      for (int i = 0; i < 4; i++) a[i] = As[k][ty * 4 + i];
#pragma unroll
      for (int j = 0; j < 4; j++) b[j] = Bs[k][tx * 4 + j];
#pragma unroll
      for (int i = 0; i < 4; i++)
#pragma unroll
        for (int j = 0; j < 4; j++) acc[i][j] += a[i] * b[j];
    }
    __syncthreads();
  }
#pragma unroll
  for (int i = 0; i < 4; i++) {
#pragma unroll
    for (int j = 0; j < 4; j++) {
      float v = acc[i][j] + (bias ? bias[n0 + tx * 4 + j] : 0.f);
      if (RELU) v = fmaxf(v, 0.f);
      C[(size_t)(m0 + ty * 4 + i) * ldc + n0 + tx * 4 + j] = v;
    }
  }
}

// ---------------- dual GEMM: blockIdx.z selects (B, C, bias) ----------------
__global__ void gemm_dual_kernel(int M, int N, int K, const float* __restrict__ A,
                                 int lda, const float* __restrict__ B0,
                                 const float* __restrict__ B1, int ldb,
                                 const float* __restrict__ bias0,
                                 float* __restrict__ C0, float* __restrict__ C1,
                                 int ldc) {
  const float* B = blockIdx.z ? B1 : B0;
  float* C = blockIdx.z ? C1 : C0;
  const float* bias = blockIdx.z ? nullptr : bias0;
  __shared__ float As[16][68];
  __shared__ float Bs[16][68];
  const int tx = threadIdx.x % 16, ty = threadIdx.x / 16;
  const int m0 = blockIdx.y * 64, n0 = blockIdx.x * 64;
  float acc[4][4] = {};
  for (int k0 = 0; k0 < K; k0 += 16) {
    for (int idx = threadIdx.x; idx < 64 * 16; idx += 256) {
      int m = idx / 16, k = idx % 16;
      As[k][m] = A[(size_t)(m0 + m) * lda + k0 + k];
    }
    for (int idx = threadIdx.x; idx < 16 * 64; idx += 256) {
      int k = idx / 64, n = idx % 64;
      Bs[k][n] = B[(size_t)(k0 + k) * ldb + n0 + n];
    }
    __syncthreads();
#pragma unroll
    for (int k = 0; k < 16; k++) {
      float a[4], b[4];
#pragma unroll
      for (int i = 0; i < 4; i++) a[i] = As[k][ty * 4 + i];
#pragma unroll
      for (int j = 0; j < 4; j++) b[j] = Bs[k][tx * 4 + j];
#pragma unroll
      for (int i = 0; i < 4; i++)
#pragma unroll
        for (int j = 0; j < 4; j++) acc[i][j] += a[i] * b[j];
    }
    __syncthreads();
  }
#pragma unroll
  for (int i = 0; i < 4; i++) {
#pragma unroll
    for (int j = 0; j < 4; j++) {
      float v = acc[i][j] + (bias ? bias[n0 + tx * 4 + j] : 0.f);
      C[(size_t)(m0 + ty * 4 + i) * ldc + n0 + tx * 4 + j] = v;
    }
  }
}

// ----------------------- cbvec: egb2 @ aW1e + ab1 ---------------------------
__global__ void cbvec_kernel(const float* __restrict__ egb2,
                             const float* __restrict__ W1,
                             const float* __restrict__ b1,
                             float* __restrict__ out) {
  const int i = threadIdx.x;  // 64
  float s = b1[i];
#pragma unroll 8
  for (int k = 0; k < ED; k++) s += egb2[k] * W1[k * AH + i];
  out[i] = s;
}

// ------------------- f32x2 edge GEMM + fused attention-0 --------------------
// Per CTA: s = blockIdx.y, d-tile [d0,d0+128), all 128 ch. 256 threads.
// Thread tile 8d x 8ch, M packs built in registers; double-buffered smem
// staging (ONE barrier per k-tile; LDGs issued a tile ahead).
#define ETS_LD 192

__global__ void __launch_bounds__(256, 2) edge_kernel(
    const float* __restrict__ a0W2, const float* __restrict__ a0b2) {
  __shared__ float asv[H4];
  __shared__ float Ts[2][16][ETS_LD];    // T tiles, skewed col(d)=d+(d>>3)*4
  __shared__ float Msm[2][16][ED];       // M tiles, natural layout
  __shared__ float xcw[AH], w2s[AH];
  float(*patt)[9] = (float(*)[9]) & Ts[0][0][0];  // epilogue alias (post-loop)

  const int s = blockIdx.y;
  const int d0 = blockIdx.x * 128;
  const int tid = threadIdx.x;

  // ---- prologue ----
  for (int i = tid; i < H4; i += 256) asv[i] = g_Amat[(size_t)s * H4 + i];
  if (tid < AH) {
    xcw[tid] = g_Xc0[s * AH + tid];  // includes cb0 + a0b1
    w2s[tid] = a0W2[tid];
  }

  const int sdd = tid >> 1;                       // staging d 0..127
  const int skh = (tid & 1) * 8;                  // staging k base
  const int scol = sdd + ((sdd >> 3) << 2);
  const float* bsrc = &g_Bmat[(size_t)(d0 + sdd) * H4];

  const int dt = (tid & 15) * 8;                  // compute d base (8 d)
  const int acol = dt + ((dt >> 3) << 2);
  const int ct = (tid >> 4) * 8;                  // compute ch base (8 ch)
  unsigned long long acc[4][8] = {};              // [d-pair][ch]

  // stage tile 0 into buffer 0
  {
    float4 b0 = *(const float4*)&bsrc[skh];
    float4 b1 = *(const float4*)&bsrc[skh + 4];
    const float4* msrc = (const float4*)&g_M[0];
    float4 mr0 = msrc[tid];
    float4 mr1 = msrc[256 + tid];
    const float* av = &asv[skh];
    Ts[0][skh + 0][scol] = fmaxf(av[0] + b0.x, 0.f);
    Ts[0][skh + 1][scol] = fmaxf(av[1] + b0.y, 0.f);
    Ts[0][skh + 2][scol] = fmaxf(av[2] + b0.z, 0.f);
    Ts[0][skh + 3][scol] = fmaxf(av[3] + b0.w, 0.f);
    Ts[0][skh + 4][scol] = fmaxf(av[4] + b1.x, 0.f);
    Ts[0][skh + 5][scol] = fmaxf(av[5] + b1.y, 0.f);
    Ts[0][skh + 6][scol] = fmaxf(av[6] + b1.z, 0.f);
    Ts[0][skh + 7][scol] = fmaxf(av[7] + b1.w, 0.f);
    ((float4*)&Msm[0][0][0])[tid] = mr0;
    ((float4*)&Msm[0][0][0])[256 + tid] = mr1;
  }
  __syncthreads();

  for (int tile = 0; tile < 64; tile++) {
    const int cur = tile & 1;
    // issue next tile's global loads (latency hidden under compute)
    float4 b0, b1, mr0, mr1;
    if (tile < 63) {
      const int kn = (tile + 1) * 16;
      b0 = *(const float4*)&bsrc[kn + skh];
      b1 = *(const float4*)&bsrc[kn + skh + 4];
      const float4* msrc = (const float4*)&g_M[(size_t)kn * ED];
      mr0 = msrc[tid];
      mr1 = msrc[256 + tid];
    }
    // compute current tile
#pragma unroll
    for (int k = 0; k < 16; k++) {
      ulonglong2 aA = *(const ulonglong2*)&Ts[cur][k][acol];
      ulonglong2 aB = *(const ulonglong2*)&Ts[cur][k][acol + 4];
      float4 m0 = *(const float4*)&Msm[cur][k][ct];
      float4 m1 = *(const float4*)&Msm[cur][k][ct + 4];
      const float mv[8] = {m0.x, m0.y, m0.z, m0.w, m1.x, m1.y, m1.z, m1.w};
#pragma unroll
      for (int c = 0; c < 8; c++) {
        const unsigned long long mm = dup2(mv[c]);
        ffma2(acc[0][c], aA.x, mm);
        ffma2(acc[1][c], aA.y, mm);
        ffma2(acc[2][c], aB.x, mm);
        ffma2(acc[3][c], aB.y, mm);
      }
    }
    // stage next tile into the other buffer
    if (tile < 63) {
      const int nb = cur ^ 1;
      const float* av = &asv[(tile + 1) * 16 + skh];
      Ts[nb][skh + 0][scol] = fmaxf(av[0] + b0.x, 0.f);
      Ts[nb][skh + 1][scol] = fmaxf(av[1] + b0.y, 0.f);
      Ts[nb][skh + 2][scol] = fmaxf(av[2] + b0.z, 0.f);
      Ts[nb][skh + 3][scol] = fmaxf(av[3] + b0.w, 0.f);
      Ts[nb][skh + 4][scol] = fmaxf(av[4] + b1.x, 0.f);
      Ts[nb][skh + 5][scol] = fmaxf(av[5] + b1.y, 0.f);
      Ts[nb][skh + 6][scol] = fmaxf(av[6] + b1.z, 0.f);
      Ts[nb][skh + 7][scol] = fmaxf(av[7] + b1.w, 0.f);
      ((float4*)&Msm[nb][0][0])[tid] = mr0;
      ((float4*)&Msm[nb][0][0])[256 + tid] = mr1;
    }
    __syncthreads();
  }

  // ---- epilogue (patt aliases Ts; loop is done, barrier passed) ----
  const int ctg = tid >> 4;  // 0..15
  if (ct < AH) {
#pragma unroll
    for (int p = 0; p < 4; p++) {
      float se = 0.f, so = 0.f;
#pragma unroll
      for (int c = 0; c < 8; c++) {
        float2 v = up2(acc[p][c]);
        se += fmaxf(v.x + xcw[ct + c], 0.f) * w2s[ct + c];
        so += fmaxf(v.y + xcw[ct + c], 0.f) * w2s[ct + c];
      }
      patt[dt + 2 * p][ctg] = se;
      patt[dt + 2 * p + 1][ctg] = so;
    }
  } else {
    const int chb = ct - AH;
#pragma unroll
    for (int p = 0; p < 4; p++) {
      float2 v0 = up2(acc[p][0]), v1 = up2(acc[p][1]);
      float2 v2 = up2(acc[p][2]), v3 = up2(acc[p][3]);
      float2 v4 = up2(acc[p][4]), v5 = up2(acc[p][5]);
      float2 v6 = up2(acc[p][6]), v7 = up2(acc[p][7]);
      const size_t base = ((size_t)s * N_NODES + d0 + dt + 2 * p) * AH + chb;
      *(float4*)&g_hid1[base] = make_float4(v0.x, v1.x, v2.x, v3.x);
      *(float4*)&g_hid1[base + 4] = make_float4(v4.x, v5.x, v6.x, v7.x);
      *(float4*)&g_hid1[base + AH] = make_float4(v0.y, v1.y, v2.y, v3.y);
      *(float4*)&g_hid1[base + AH + 4] = make_float4(v4.y, v5.y, v6.y, v7.y);
    }
  }
  __syncthreads();
  if (tid < 128) {
    float v = 0.f;
#pragma unroll
    for (int g = 0; g < 8; g++) v += patt[tid][g];
    float att = (d0 + tid == s) ? 0.f : 1.f / (1.f + expf(-(v + a0b2[0])));
    g_Att0T[(size_t)(d0 + tid) * N_NODES + s] = att;
  }
}

// ------------------ attention layer 1 row-sums w[s] -------------------------
__global__ void att1w_kernel(const float* __restrict__ a1W1,
                             const float* __restrict__ a1W2,
                             const float* __restrict__ a1b2) {
  const int s = blockIdx.x;
  const int warp = threadIdx.x >> 5, lane = threadIdx.x & 31;
  __shared__ float pxc[AH][5];
  __shared__ float xc[AH], w2[AH];
  __shared__ float wsum[8];
  {  // xc1 partials: x1[s] @ a1W1x
    const int i = threadIdx.x >> 2, q = threadIdx.x & 3;
    const float* xs = &g_x1[s * H + q * 64];
    const float* wcol = &a1W1[(size_t)(ED + q * 64) * AH + i];
    float acc = 0.f;
#pragma unroll 8
    for (int k = 0; k < 64; k++) acc += xs[k] * wcol[k * AH];
    pxc[i][q] = acc;
  }
  __syncthreads();
  if (threadIdx.x < AH) {
    xc[threadIdx.x] = pxc[threadIdx.x][0] + pxc[threadIdx.x][1] +
                      pxc[threadIdx.x][2] + pxc[threadIdx.x][3] +
                      g_cb1[threadIdx.x];
    w2[threadIdx.x] = a1W2[threadIdx.x];
  }
  __syncthreads();
  const float b2 = a1b2[0];
  float accv = 0.f;
  for (int d = warp; d < N_NODES; d += 8) {
    float2 h2 = *(const float2*)&g_hid1[(((size_t)s) * N_NODES + d) * AH + lane * 2];
    float v = fmaxf(h2.x + xc[lane * 2], 0.f) * w2[lane * 2] +
              fmaxf(h2.y + xc[lane * 2 + 1], 0.f) * w2[lane * 2 + 1];
    for (int o = 16; o > 0; o >>= 1) v += __shfl_down_sync(0xffffffffu, v, o);
    if (lane == 0 && d != s) accv += 1.f / (1.f + expf(-(v + b2)));
  }
  if (lane == 0) wsum[warp] = accv;
  __syncthreads();
  if (threadIdx.x == 0) {
    float t = 0.f;
    for (int i = 0; i < 8; i++) t += wsum[i];
    g_w[s] = t;
  }
}

// --------------------------- final reduction --------------------------------
__global__ void final_kernel(const float* __restrict__ c1W,
                             const float* __restrict__ c1b,
                             float* __restrict__ out) {
  __shared__ float v[H];
  __shared__ float wsh[N_NODES];
  const int tid = threadIdx.x;  // 256
  for (int i = tid; i < N_NODES; i += blockDim.x) wsh[i] = g_w[i];
  __syncthreads();
  float s = 0.f;
  for (int n = 0; n < N_NODES; n++) s += wsh[n] * g_x1[n * H + tid];
  v[tid] = s;
  __syncthreads();
  float o = (float)N_NODES * c1b[tid];
  for (int h = 0; h < H; h++) o += v[h] * c1W[h * H + tid];
  out[tid] = o;
}

// ------------------------------- launcher -----------------------------------
static float* sym_addr(const void* symbol) {
  void* p = nullptr;
  cudaGetSymbolAddress(&p, symbol);
  return (float*)p;
}

extern "C" void kernel_launch(void* const* d_in, const int* in_sizes, int n_in,
                              void* d_out, int out_size) {
  const float* z = (const float*)d_in[0];
  const float* Wih = (const float*)d_in[1];
  const float* Whh = (const float*)d_in[2];
  const float* bih = (const float*)d_in[3];
  const float* bhh = (const float*)d_in[4];
  const float* egW1 = (const float*)d_in[5];
  const float* egb1 = (const float*)d_in[6];
  const float* egW2 = (const float*)d_in[7];
  const float* egb2 = (const float*)d_in[8];
  const float* a0W1 = (const float*)d_in[9];
  const float* a0b1 = (const float*)d_in[10];
  const float* a0W2 = (const float*)d_in[11];
  const float* a0b2 = (const float*)d_in[12];
  const float* a1W1 = (const float*)d_in[13];
  const float* a1b1 = (const float*)d_in[14];
  const float* a1W2 = (const float*)d_in[15];
  const float* a1b2 = (const float*)d_in[16];
  const float* c0W = (const float*)d_in[17];
  const float* c0b = (const float*)d_in[18];
  const float* c1W = (const float*)d_in[19];
  const float* c1b = (const float*)d_in[20];
  float* out = (float*)d_out;

  float* nodes = sym_addr(g_nodes);
  float* Amat = sym_addr(g_Amat);
  float* Bmat = sym_addr(g_Bmat);
  float* Mmat = sym_addr(g_M);
  float* cb0 = sym_addr(g_cb0);
  float* cb1 = sym_addr(g_cb1);
  float* Xc0 = sym_addr(g_Xc0);
  float* Att0T = sym_addr(g_Att0T);
  float* agg0 = sym_addr(g_agg0);
  float* x1 = sym_addr(g_x1);

  // 0: M = eg_W2 @ [a0W1e | a1W1e]  (GRU-independent)
  gemm_dual_kernel<<<dim3(1, H4 / 64, 2), 256>>>(
      H4, AH, ED, egW2, ED, a0W1, a1W1, AH, nullptr, Mmat, Mmat + AH, ED);

  // 1-2: cb vectors (GRU-independent)
  cbvec_kernel<<<1, AH>>>(egb2, a0W1, a0b1, cb0);
  cbvec_kernel<<<1, AH>>>(egb2, a1W1, a1b1, cb1);

  // 3 (PROFILED): GRU -> nodes
  gru_kernel<<<GRU_CTAS, 384>>>(z, Wih, Whh, bih, bhh);

  // 4: A = nodes@W1a + eg_b1 ; B = nodes@W1b
  gemm_dual_kernel<<<dim3(H4 / 64, N_NODES / 64, 2), 256>>>(
      N_NODES, H4, H, nodes, H, egW1, egW1 + (size_t)H * H4, H4, egb1, Amat,
      Bmat, H4);

  // 5: Xc0 = nodes @ a0W1x + cb0
  gemm_kernel<false><<<dim3(1, N_NODES / 64), 256>>>(
      N_NODES, AH, H, nodes, H, a0W1 + (size_t)ED * AH, AH, cb0, Xc0, AH);

  // 6: edge GEMM (f32x2, double-buffered) + fused att0
  edge_kernel<<<dim3(N_NODES / 128, N_NODES), 256>>>(a0W2, a0b2);

  // 7-8: agg0 = Att0T @ nodes ; x1 = relu(agg0 @ c0W + c0b)
  gemm_kernel<false><<<dim3(H / 64, N_NODES / 64), 256>>>(
      N_NODES, H, N_NODES, Att0T, N_NODES, nodes, H, nullptr, agg0, H);
  gemm_kernel<true><<<dim3(H / 64, N_NODES / 64), 256>>>(
      N_NODES, H, H, agg0, H, c0W, H, c0b, x1, H);

  // 9: w[s] = sum_d att1(s,d)
  att1w_kernel<<<N_NODES, 256>>>(a1W1, a1W2, a1b2);

  // 10: out = (sum_s w[s] x1[s]) @ c1W + 384*c1b
  final_kernel<<<1, H>>>(c1W, c1b, out);
}